// round 8
// baseline (speedup 1.0000x reference)
#include <cuda_runtime.h>
#include <cstddef>

#define Bsz  1024
#define Tsz  128
#define Isz  128
#define Hsz  256
#define G3   768
#define Ksz  8
#define E1sz 512
#define E2sz 256

typedef unsigned long long u64;
struct alignas(16) U64x2 { u64 lo, hi; };

__device__ __forceinline__ u64 ffma2(u64 a, u64 b, u64 c){
    u64 d; asm("fma.rn.f32x2 %0, %1, %2, %3;" : "=l"(d) : "l"(a), "l"(b), "l"(c)); return d;
}
__device__ __forceinline__ void unpack2(u64 v, float& lo, float& hi){
    asm("mov.b64 {%0, %1}, %2;" : "=f"(lo), "=f"(hi) : "l"(v));
}
__device__ __forceinline__ u64 pack2(float x, float y){
    u64 v; asm("mov.b64 %0, {%1, %2};" : "=l"(v) : "f"(x), "f"(y)); return v;
}
__device__ __forceinline__ float sigmoidf_(float x){
    return __fdividef(1.0f, 1.0f + __expf(-x));
}
__device__ __forceinline__ float tanhf_(float x){
    return 1.0f - __fdividef(2.0f, __expf(2.0f * x) + 1.0f);
}

// ---------------- scratch ----------------
__device__ float g_xT[(size_t)Tsz * Isz * Bsz];      // [t][k][b]
__device__ float g_WihT0[(size_t)Isz * G3];
__device__ float g_WhhT0[(size_t)Hsz * G3];
__device__ float g_WihT1[(size_t)Hsz * G3];
__device__ float g_WhhT1[(size_t)Hsz * G3];
__device__ float g_gi0[(size_t)Tsz * Bsz * G3];
__device__ float g_gi1[(size_t)Tsz * Bsz * G3];
__device__ float g_hl0T[2][(size_t)Hsz * Bsz];       // ping-pong [h][b]
__device__ float g_h1T[2][(size_t)Hsz * Bsz];
__device__ float g_z[(size_t)Bsz * Hsz];
__device__ float g_q[Bsz * Ksz];
__device__ float g_e1[(size_t)Ksz * Bsz * E1sz];
__device__ float g_e2[(size_t)Ksz * Bsz * E2sz];

// barrier state (zero-init; self-maintaining across launches: counters return to
// 0 after every completed barrier, generation targets are entry-relative)
__device__ unsigned g_cnt0, g_gen0, g_cnt1, g_gen1;

// ---------------- software grid barrier (all CTAs resident by construction) ---
__device__ __forceinline__ void grid_bar(unsigned* cnt, volatile unsigned* gen,
                                         unsigned target, unsigned nCTAm1){
    __syncthreads();
    if (threadIdx.x == 0){
        __threadfence();
        if (atomicAdd(cnt, 1u) == nCTAm1){
            atomicExch(cnt, 0u);
            __threadfence();
            *gen = target;
        } else {
            while (*gen < target) { }
        }
        __threadfence();
    }
    __syncthreads();
}

// ---------------- strided 32x32 transpose: out[c][r] = in[r][c] ----------------
__global__ void __launch_bounds__(256) transpose_s(
    const float* __restrict__ in, size_t inRS, size_t inZ,
    float* __restrict__ out, size_t outRS, size_t outZ)
{
    in  += (size_t)blockIdx.z * inZ;
    out += (size_t)blockIdx.z * outZ;
    __shared__ float t[32][33];
    const int tx = threadIdx.x & 31, ty = threadIdx.x >> 5;
    const int r0 = blockIdx.y * 32, c0 = blockIdx.x * 32;
    #pragma unroll
    for (int i = 0; i < 4; i++)
        t[ty + 8 * i][tx] = in[(size_t)(r0 + ty + 8 * i) * inRS + c0 + tx];
    __syncthreads();
    #pragma unroll
    for (int i = 0; i < 4; i++)
        out[(size_t)(c0 + ty + 8 * i) * outRS + r0 + tx] = t[tx][ty + 8 * i];
}

// ---------------------------------------------------------------------------
// TN GEMM (for gi0): C[m][n] = sum_k AT(k,m) * WT[k][n]
// ---------------------------------------------------------------------------
__global__ void __launch_bounds__(256) gemm_tn(
    const float* __restrict__ AT, size_t aRowStride, size_t aBlkStride, int mBlk,
    const float* __restrict__ WT, int N, int K, float* __restrict__ C)
{
    extern __shared__ float sm[];
    float* As = sm;              // [64][128]
    float* Bs = sm + 64 * 128;   // [64][64]
    const int tid = threadIdx.x, w = tid >> 5, lane = tid & 31;
    const int m0 = blockIdx.x * 128, n0 = blockIdx.y * 64;
    const int jl = w * 8;
    const float* Abase = AT + (size_t)(m0 / mBlk) * aBlkStride + (m0 % mBlk);

    u64 acc[4][4];
    #pragma unroll
    for (int r = 0; r < 4; r++)
        #pragma unroll
        for (int q = 0; q < 4; q++) acc[r][q] = 0ull;

    for (int kk = 0; kk < K; kk += 64){
        __syncthreads();
        for (int i = tid; i < 64 * 32; i += 256){
            int k = i >> 5, q = i & 31;
            *reinterpret_cast<float4*>(As + k * 128 + q * 4) =
                *reinterpret_cast<const float4*>(Abase + (size_t)(kk + k) * aRowStride + q * 4);
        }
        for (int i = tid; i < 64 * 16; i += 256){
            int k = i >> 4, q = i & 15;
            *reinterpret_cast<float4*>(Bs + k * 64 + q * 4) =
                *reinterpret_cast<const float4*>(WT + (size_t)(kk + k) * N + n0 + q * 4);
        }
        __syncthreads();
        #pragma unroll 8
        for (int k = 0; k < 64; k++){
            U64x2 ap = *reinterpret_cast<const U64x2*>(As + k * 128 + 4 * lane);
            float f0, f1, f2, f3;
            unpack2(ap.lo, f0, f1); unpack2(ap.hi, f2, f3);
            u64 ad[4] = { pack2(f0, f0), pack2(f1, f1), pack2(f2, f2), pack2(f3, f3) };
            U64x2 b01 = *reinterpret_cast<const U64x2*>(Bs + k * 64 + jl);
            U64x2 b23 = *reinterpret_cast<const U64x2*>(Bs + k * 64 + jl + 4);
            u64 bq[4] = { b01.lo, b01.hi, b23.lo, b23.hi };
            #pragma unroll
            for (int r = 0; r < 4; r++)
                #pragma unroll
                for (int q = 0; q < 4; q++)
                    acc[r][q] = ffma2(ad[r], bq[q], acc[r][q]);
        }
    }

    #pragma unroll
    for (int r = 0; r < 4; r++){
        int row = m0 + 4 * lane + r;
        float o[8];
        #pragma unroll
        for (int q = 0; q < 4; q++) unpack2(acc[r][q], o[2 * q], o[2 * q + 1]);
        *reinterpret_cast<float4*>(C + (size_t)row * N + n0 + jl) =
            make_float4(o[0], o[1], o[2], o[3]);
        *reinterpret_cast<float4*>(C + (size_t)row * N + n0 + jl + 4) =
            make_float4(o[4], o[5], o[6], o[7]);
    }
}

// ---------------------------------------------------------------------------
// Persistent GRU layer: all 128 steps in ONE kernel, grid (16,8)=128 CTAs,
// software grid barrier between steps. Weight slices live in smem for the
// whole layer. FUSE: also emits gi1[t-1] = h[t-1] @ Wih1^T per step, and the
// final gi1[127] in a tail phase.
// All h arrays transposed [256][1024]; h reads via __ldcg (cross-CTA in-kernel).
// ---------------------------------------------------------------------------
template<bool FUSE>
__global__ void __launch_bounds__(256) gru_persist(
    const float* __restrict__ WhhT, const float* __restrict__ WihTn,
    const float* __restrict__ giAll,
    const float* __restrict__ bih, const float* __restrict__ bhh,
    float* __restrict__ hbuf,        // [2][256][1024]
    float* __restrict__ gi1out,      // [T][B][768] (FUSE only)
    unsigned* cnt, unsigned* genp)
{
    extern __shared__ float sm[];
    float* Bhh = sm;                                 // [256][96]
    float* Bih = sm + 256 * 96;                      // [256][96] (FUSE)
    float* As  = sm + (FUSE ? 2 : 1) * 256 * 96;     // [64][64]
    const int tid = threadIdx.x, w = tid >> 5, lane = tid & 31;
    const int m0 = blockIdx.x * 64, n0 = blockIdx.y * 32;
    const int jl = w * 4, ml = lane * 2;
    const size_t PH = (size_t)Hsz * Bsz, PG = (size_t)Bsz * G3;

    // ---- one-time weight slice load ----
    for (int i = tid; i < 256 * 24; i += 256){
        int k = i / 24, c = i - k * 24, g = c >> 3, q = c & 7;
        *reinterpret_cast<float4*>(Bhh + k * 96 + g * 32 + q * 4) =
            *reinterpret_cast<const float4*>(WhhT + (size_t)k * G3 + g * Hsz + n0 + q * 4);
        if constexpr (FUSE)
            *reinterpret_cast<float4*>(Bih + k * 96 + g * 32 + q * 4) =
                *reinterpret_cast<const float4*>(WihTn + (size_t)k * G3 + g * Hsz + n0 + q * 4);
    }

    float bi[3][4], bh_[3][4];
    #pragma unroll
    for (int g = 0; g < 3; g++){
        *reinterpret_cast<float4*>(bi[g]) =
            *reinterpret_cast<const float4*>(bih + g * Hsz + n0 + jl);
        *reinterpret_cast<float4*>(bh_[g]) =
            *reinterpret_cast<const float4*>(bhh + g * Hsz + n0 + jl);
    }

    volatile unsigned* gen = genp;
    const unsigned gbase = *gen;     // entry-relative generation base
    __syncthreads();

    for (int t = 0; t < Tsz; t++){
        const float* HprevT = hbuf + (size_t)((t - 1) & 1) * PH;   // unused at t=0
        float*       HnewT  = hbuf + (size_t)(t & 1) * PH;
        const float* gi     = giAll + (size_t)t * PG;

        u64 aH[3][2][2], aI[3][2][2];
        #pragma unroll
        for (int g = 0; g < 3; g++)
            #pragma unroll
            for (int cp = 0; cp < 2; cp++)
                #pragma unroll
                for (int r = 0; r < 2; r++){ aH[g][cp][r] = 0ull; aI[g][cp][r] = 0ull; }

        if (t > 0){
            for (int kk = 0; kk < Hsz; kk += 64){
                __syncthreads();
                for (int i = tid; i < 64 * 16; i += 256){
                    int k = i >> 4, q = i & 15;
                    *reinterpret_cast<float4*>(As + k * 64 + q * 4) =
                        __ldcg(reinterpret_cast<const float4*>(
                            HprevT + (size_t)(kk + k) * Bsz + m0 + q * 4));
                }
                __syncthreads();
                #pragma unroll 8
                for (int k = 0; k < 64; k++){
                    u64 a01 = *reinterpret_cast<const u64*>(As + k * 64 + ml);
                    float a0f, a1f; unpack2(a01, a0f, a1f);
                    u64 a0 = pack2(a0f, a0f), a1 = pack2(a1f, a1f);
                    const float* bh = Bhh + (size_t)(kk + k) * 96 + jl;
                    #pragma unroll
                    for (int g = 0; g < 3; g++){
                        U64x2 bb = *reinterpret_cast<const U64x2*>(bh + g * 32);
                        aH[g][0][0] = ffma2(a0, bb.lo, aH[g][0][0]);
                        aH[g][0][1] = ffma2(a1, bb.lo, aH[g][0][1]);
                        aH[g][1][0] = ffma2(a0, bb.hi, aH[g][1][0]);
                        aH[g][1][1] = ffma2(a1, bb.hi, aH[g][1][1]);
                    }
                    if constexpr (FUSE){
                        const float* bi2 = Bih + (size_t)(kk + k) * 96 + jl;
                        #pragma unroll
                        for (int g = 0; g < 3; g++){
                            U64x2 bb = *reinterpret_cast<const U64x2*>(bi2 + g * 32);
                            aI[g][0][0] = ffma2(a0, bb.lo, aI[g][0][0]);
                            aI[g][0][1] = ffma2(a1, bb.lo, aI[g][0][1]);
                            aI[g][1][0] = ffma2(a0, bb.hi, aI[g][1][0]);
                            aI[g][1][1] = ffma2(a1, bb.hi, aI[g][1][1]);
                        }
                    }
                }
            }
        }

        // ---- epilogue ----
        float gh[3][2][4];
        if (t > 0){
            #pragma unroll
            for (int g = 0; g < 3; g++)
                #pragma unroll
                for (int cp = 0; cp < 2; cp++)
                    #pragma unroll
                    for (int r = 0; r < 2; r++)
                        unpack2(aH[g][cp][r], gh[g][r][2 * cp], gh[g][r][2 * cp + 1]);
        } else {
            #pragma unroll
            for (int g = 0; g < 3; g++)
                #pragma unroll
                for (int r = 0; r < 2; r++)
                    #pragma unroll
                    for (int c = 0; c < 4; c++) gh[g][r][c] = 0.0f;
        }

        float hp[2][4];
        #pragma unroll
        for (int r = 0; r < 2; r++)
            #pragma unroll
            for (int c = 0; c < 4; c++) hp[r][c] = 0.0f;
        if (t > 0){
            #pragma unroll
            for (int c = 0; c < 4; c++){
                float2 v = __ldcg(reinterpret_cast<const float2*>(
                    HprevT + (size_t)(n0 + jl + c) * Bsz + m0 + ml));
                hp[0][c] = v.x; hp[1][c] = v.y;
            }
        }

        float hn[2][4];
        #pragma unroll
        for (int r = 0; r < 2; r++){
            const float* gr = gi + (size_t)(m0 + ml + r) * G3;
            float gv[3][4];
            #pragma unroll
            for (int g = 0; g < 3; g++)
                *reinterpret_cast<float4*>(gv[g]) =
                    *reinterpret_cast<const float4*>(gr + g * Hsz + n0 + jl);
            #pragma unroll
            for (int c = 0; c < 4; c++){
                float rg = sigmoidf_(gv[0][c] + bi[0][c] + gh[0][r][c] + bh_[0][c]);
                float zg = sigmoidf_(gv[1][c] + bi[1][c] + gh[1][r][c] + bh_[1][c]);
                float ng = tanhf_(gv[2][c] + bi[2][c] + rg * (gh[2][r][c] + bh_[2][c]));
                hn[r][c] = (1.0f - zg) * ng + zg * hp[r][c];
            }
        }
        #pragma unroll
        for (int c = 0; c < 4; c++)
            *reinterpret_cast<float2*>(HnewT + (size_t)(n0 + jl + c) * Bsz + m0 + ml) =
                make_float2(hn[0][c], hn[1][c]);

        if constexpr (FUSE){
            if (t > 0){
                #pragma unroll
                for (int r = 0; r < 2; r++){
                    float* go = gi1out + (size_t)(t - 1) * PG + (size_t)(m0 + ml + r) * G3;
                    #pragma unroll
                    for (int g = 0; g < 3; g++){
                        float o0, o1, o2, o3;
                        unpack2(aI[g][0][r], o0, o1);
                        unpack2(aI[g][1][r], o2, o3);
                        *reinterpret_cast<float4*>(go + g * Hsz + n0 + jl) =
                            make_float4(o0, o1, o2, o3);
                    }
                }
            }
        }

        grid_bar(cnt, gen, gbase + (unsigned)t + 1u, 127u);
    }

    // ---- FUSE tail: gi1[127] = h[127] @ Wih1^T ----
    if constexpr (FUSE){
        const float* HpT = hbuf + PH;   // h[127] lives in buffer (127&1)=1
        u64 aI[3][2][2];
        #pragma unroll
        for (int g = 0; g < 3; g++)
            #pragma unroll
            for (int cp = 0; cp < 2; cp++){ aI[g][cp][0] = 0ull; aI[g][cp][1] = 0ull; }
        for (int kk = 0; kk < Hsz; kk += 64){
            __syncthreads();
            for (int i = tid; i < 64 * 16; i += 256){
                int k = i >> 4, q = i & 15;
                *reinterpret_cast<float4*>(As + k * 64 + q * 4) =
                    __ldcg(reinterpret_cast<const float4*>(
                        HpT + (size_t)(kk + k) * Bsz + m0 + q * 4));
            }
            __syncthreads();
            #pragma unroll 8
            for (int k = 0; k < 64; k++){
                u64 a01 = *reinterpret_cast<const u64*>(As + k * 64 + ml);
                float a0f, a1f; unpack2(a01, a0f, a1f);
                u64 a0 = pack2(a0f, a0f), a1 = pack2(a1f, a1f);
                const float* bi2 = Bih + (size_t)(kk + k) * 96 + jl;
                #pragma unroll
                for (int g = 0; g < 3; g++){
                    U64x2 bb = *reinterpret_cast<const U64x2*>(bi2 + g * 32);
                    aI[g][0][0] = ffma2(a0, bb.lo, aI[g][0][0]);
                    aI[g][0][1] = ffma2(a1, bb.lo, aI[g][0][1]);
                    aI[g][1][0] = ffma2(a0, bb.hi, aI[g][1][0]);
                    aI[g][1][1] = ffma2(a1, bb.hi, aI[g][1][1]);
                }
            }
        }
        #pragma unroll
        for (int r = 0; r < 2; r++){
            float* go = gi1out + (size_t)127 * PG + (size_t)(m0 + ml + r) * G3;
            #pragma unroll
            for (int g = 0; g < 3; g++){
                float o0, o1, o2, o3;
                unpack2(aI[g][0][r], o0, o1);
                unpack2(aI[g][1][r], o2, o3);
                *reinterpret_cast<float4*>(go + g * Hsz + n0 + jl) =
                    make_float4(o0, o1, o2, o3);
            }
        }
    }
}

// ---------------------------------------------------------------------------
// Per-expert NT GEMM + relu (proven)
// ---------------------------------------------------------------------------
__global__ void __launch_bounds__(256) gemm_relu_kernel(
    const float* __restrict__ Abase, size_t aStride,
    const float* __restrict__ Wbase, size_t wStride,
    const float* __restrict__ biasBase, size_t bStride,
    float* __restrict__ Cbase, size_t cStride,
    int Kdim, int Ndim)
{
    const int e = blockIdx.z;
    const float* A    = Abase    + (size_t)e * aStride;
    const float* W    = Wbase    + (size_t)e * wStride;
    const float* bias = biasBase + (size_t)e * bStride;
    float*       C    = Cbase    + (size_t)e * cStride;

    const int m0 = blockIdx.x * 64, n0 = blockIdx.y * 64;
    const int tid = threadIdx.x, tx = tid & 15, ty = tid >> 4;

    __shared__ float2 As[32][64];
    __shared__ float  Ws[32][64];

    u64 acc[4][2];
    #pragma unroll
    for (int r = 0; r < 4; r++){ acc[r][0] = 0ull; acc[r][1] = 0ull; }

    for (int kk = 0; kk < Kdim; kk += 32){
        __syncthreads();
        {
            int row = tid >> 2;
            const float* ar = A + (size_t)(m0 + row) * Kdim + kk;
            const float* wr = W + (size_t)(n0 + row) * Kdim + kk;
            #pragma unroll
            for (int hh = 0; hh < 2; hh++){
                int kb = ((tid & 3) << 2) + (hh << 4);
                float4 va = *reinterpret_cast<const float4*>(ar + kb);
                As[kb + 0][row] = make_float2(va.x, va.x);
                As[kb + 1][row] = make_float2(va.y, va.y);
                As[kb + 2][row] = make_float2(va.z, va.z);
                As[kb + 3][row] = make_float2(va.w, va.w);
                float4 vw = *reinterpret_cast<const float4*>(wr + kb);
                Ws[kb + 0][row] = vw.x;
                Ws[kb + 1][row] = vw.y;
                Ws[kb + 2][row] = vw.z;
                Ws[kb + 3][row] = vw.w;
            }
        }
        __syncthreads();
        #pragma unroll 8
        for (int k = 0; k < 32; k++){
            u64 b0 = *reinterpret_cast<const u64*>(&Ws[k][tx << 1]);
            u64 b1 = *reinterpret_cast<const u64*>(&Ws[k][(tx << 1) + 32]);
            #pragma unroll
            for (int r = 0; r < 4; r++){
                u64 a = *reinterpret_cast<const u64*>(&As[k][(ty << 2) + r]);
                acc[r][0] = ffma2(a, b0, acc[r][0]);
                acc[r][1] = ffma2(a, b1, acc[r][1]);
            }
        }
    }

    #pragma unroll
    for (int r = 0; r < 4; r++){
        int row = m0 + (ty << 2) + r;
        #pragma unroll
        for (int p = 0; p < 2; p++){
            int j = (tx << 1) + (p << 5);
            float c0, c1;
            unpack2(acc[r][p], c0, c1);
            c0 = fmaxf(c0 + bias[n0 + j],     0.0f);
            c1 = fmaxf(c1 + bias[n0 + j + 1], 0.0f);
            *reinterpret_cast<float2*>(&C[(size_t)row * Ndim + n0 + j]) = make_float2(c0, c1);
        }
    }
}

// ---------------- soft clustering (proven) ----------------
__global__ void __launch_bounds__(256) qkernel(
    const float* __restrict__ z, const float* __restrict__ cent, float* __restrict__ q)
{
    int warp = threadIdx.x >> 5, lane = threadIdx.x & 31;
    int b = blockIdx.x * 8 + warp;
    float zr[8];
    #pragma unroll
    for (int i = 0; i < 8; i++) zr[i] = z[(size_t)b * Hsz + lane + 32 * i];
    float s = 0.0f;
    for (int k = 0; k < Ksz; k++){
        float d = 0.0f;
        #pragma unroll
        for (int i = 0; i < 8; i++){
            float t = zr[i] - cent[k * Hsz + lane + 32 * i];
            d = fmaf(t, t, d);
        }
        #pragma unroll
        for (int off = 16; off; off >>= 1) d += __shfl_xor_sync(0xffffffffu, d, off);
        if (lane == k) s = 1.0f / (1.0f + d);
    }
    float tot = s;
    #pragma unroll
    for (int off = 16; off; off >>= 1) tot += __shfl_xor_sync(0xffffffffu, tot, off);
    if (lane < Ksz) q[(size_t)b * Ksz + lane] = s / tot;
}

// ---------------- logits + combine (proven) ----------------
__global__ void __launch_bounds__(256) combine_kernel(
    const float* __restrict__ h2, const float* __restrict__ q,
    const float* __restrict__ eW3, const float* __restrict__ eb3,
    float* __restrict__ out)
{
    int warp = threadIdx.x >> 5, lane = threadIdx.x & 31;
    int b = blockIdx.x * 8 + warp;
    float acc[Ksz][2];
    #pragma unroll
    for (int k = 0; k < Ksz; k++){ acc[k][0] = 0.0f; acc[k][1] = 0.0f; }
    for (int f = lane; f < E2sz; f += 32){
        #pragma unroll
        for (int k = 0; k < Ksz; k++){
            float hv = h2[((size_t)k * Bsz + b) * E2sz + f];
            acc[k][0] = fmaf(hv, eW3[(size_t)(k * 2 + 0) * E2sz + f], acc[k][0]);
            acc[k][1] = fmaf(hv, eW3[(size_t)(k * 2 + 1) * E2sz + f], acc[k][1]);
        }
    }
    #pragma unroll
    for (int k = 0; k < Ksz; k++)
        #pragma unroll
        for (int c = 0; c < 2; c++)
            #pragma unroll
            for (int off = 16; off; off >>= 1)
                acc[k][c] += __shfl_xor_sync(0xffffffffu, acc[k][c], off);
    if (lane == 0){
        float p0 = 0.0f, p1 = 0.0f;
        #pragma unroll
        for (int k = 0; k < Ksz; k++){
            float qq = q[(size_t)b * Ksz + k];
            p0 = fmaf(qq, acc[k][0] + eb3[k * 2 + 0], p0);
            p1 = fmaf(qq, acc[k][1] + eb3[k * 2 + 1], p1);
        }
        out[b * 2 + 0] = p0;
        out[b * 2 + 1] = p1;
    }
}

// ---------------------------------------------------------------------------
#define PERSIST_SMEM_FUSE   ((2 * 256 * 96 + 64 * 64) * 4)   /* 212992 */
#define PERSIST_SMEM_PLAIN  ((256 * 96 + 64 * 64) * 4)       /* 114688 */
#define GEMM_SMEM           ((64 * 128 + 64 * 64) * 4)       /* 49152  */

extern "C" void kernel_launch(void* const* d_in, const int* in_sizes, int n_in,
                              void* d_out, int out_size)
{
    const float* x    = (const float*)d_in[0];
    const float* Wih0 = (const float*)d_in[1];
    const float* Whh0 = (const float*)d_in[2];
    const float* bih0 = (const float*)d_in[3];
    const float* bhh0 = (const float*)d_in[4];
    const float* Wih1 = (const float*)d_in[5];
    const float* Whh1 = (const float*)d_in[6];
    const float* bih1 = (const float*)d_in[7];
    const float* bhh1 = (const float*)d_in[8];
    const float* cent = (const float*)d_in[9];
    const float* eW1  = (const float*)d_in[10];
    const float* eb1  = (const float*)d_in[11];
    const float* eW2  = (const float*)d_in[12];
    const float* eb2  = (const float*)d_in[13];
    const float* eW3  = (const float*)d_in[14];
    const float* eb3  = (const float*)d_in[15];
    float* out = (float*)d_out;

    float *xT, *WihT0, *WhhT0, *WihT1, *WhhT1, *gi0, *gi1, *hl0T, *h1T, *z, *qb, *e1, *e2;
    unsigned *cnt0, *gen0, *cnt1, *gen1;
    cudaGetSymbolAddress((void**)&xT,    g_xT);
    cudaGetSymbolAddress((void**)&WihT0, g_WihT0);
    cudaGetSymbolAddress((void**)&WhhT0, g_WhhT0);
    cudaGetSymbolAddress((void**)&WihT1, g_WihT1);
    cudaGetSymbolAddress((void**)&WhhT1, g_WhhT1);
    cudaGetSymbolAddress((void**)&gi0,   g_gi0);
    cudaGetSymbolAddress((void**)&gi1,   g_gi1);
    cudaGetSymbolAddress((void**)&hl0T,  g_hl0T);
    cudaGetSymbolAddress((void**)&h1T,   g_h1T);
    cudaGetSymbolAddress((void**)&z,     g_z);
    cudaGetSymbolAddress((void**)&qb,    g_q);
    cudaGetSymbolAddress((void**)&e1,    g_e1);
    cudaGetSymbolAddress((void**)&e2,    g_e2);
    cudaGetSymbolAddress((void**)&cnt0,  g_cnt0);
    cudaGetSymbolAddress((void**)&gen0,  g_gen0);
    cudaGetSymbolAddress((void**)&cnt1,  g_cnt1);
    cudaGetSymbolAddress((void**)&gen1,  g_gen1);

    cudaFuncSetAttribute(gru_persist<true>,
                         cudaFuncAttributeMaxDynamicSharedMemorySize, PERSIST_SMEM_FUSE);
    cudaFuncSetAttribute(gru_persist<false>,
                         cudaFuncAttributeMaxDynamicSharedMemorySize, PERSIST_SMEM_PLAIN);
    cudaFuncSetAttribute(gemm_tn,
                         cudaFuncAttributeMaxDynamicSharedMemorySize, GEMM_SMEM);

    const size_t PH = (size_t)Hsz * Bsz;
    dim3 sg(16, 8);

    // ---- one-time layout transforms ----
    transpose_s<<<dim3(4, 32, 128), 256>>>(x, (size_t)Tsz * Isz, (size_t)Isz,
                                           xT, (size_t)Bsz, (size_t)Isz * Bsz);
    transpose_s<<<dim3(4, 24, 1), 256>>>(Wih0, Isz, 0, WihT0, G3, 0);
    transpose_s<<<dim3(8, 24, 1), 256>>>(Whh0, Hsz, 0, WhhT0, G3, 0);
    transpose_s<<<dim3(8, 24, 1), 256>>>(Wih1, Hsz, 0, WihT1, G3, 0);
    transpose_s<<<dim3(8, 24, 1), 256>>>(Whh1, Hsz, 0, WhhT1, G3, 0);

    // ---- gi0 = x @ Wih0^T : M=131072, K=128, N=768 ----
    gemm_tn<<<dim3(1024, 12), 256, GEMM_SMEM>>>(
        xT, (size_t)Bsz, (size_t)Isz * Bsz, Bsz, WihT0, G3, Isz, gi0);

    // ---- layer 0: persistent 128-step chain (emits gi1 as it goes) ----
    gru_persist<true><<<sg, 256, PERSIST_SMEM_FUSE>>>(
        WhhT0, WihT1, gi0, bih0, bhh0, hl0T, gi1, cnt0, gen0);

    // ---- layer 1: persistent 128-step chain ----
    gru_persist<false><<<sg, 256, PERSIST_SMEM_PLAIN>>>(
        WhhT1, nullptr, gi1, bih1, bhh1, h1T, nullptr, cnt1, gen1);

    // ---- z = h1T[1]^T  ([256][1024] -> [1024][256]) ----
    transpose_s<<<dim3(32, 8, 1), 256>>>(h1T + PH, Bsz, 0, z, Hsz, 0);

    // ---- clustering + experts + combine ----
    qkernel<<<128, 256>>>(z, cent, qb);
    gemm_relu_kernel<<<dim3(16, 8, 8), 256>>>(
        z, (size_t)0, eW1, (size_t)E1sz * Hsz, eb1, (size_t)E1sz,
        e1, (size_t)Bsz * E1sz, Hsz, E1sz);
    gemm_relu_kernel<<<dim3(16, 4, 8), 256>>>(
        e1, (size_t)Bsz * E1sz, eW2, (size_t)E2sz * E1sz, eb2, (size_t)E2sz,
        e2, (size_t)Bsz * E2sz, E1sz, E2sz);
    combine_kernel<<<128, 256>>>(e2, qb, eW3, eb3, out);

    (void)in_sizes; (void)n_in; (void)out_size;
}

// round 9
// speedup vs baseline: 1.8757x; 1.8757x over previous
#include <cuda_runtime.h>
#include <cuda_bf16.h>
#include <cstddef>

#define Bsz  1024
#define Tsz  128
#define Isz  128
#define Hsz  256
#define G3   768
#define Ksz  8
#define E1sz 512
#define E2sz 256

typedef unsigned long long u64;
typedef unsigned int u32;
struct alignas(16) U64x2 { u64 lo, hi; };

__device__ __forceinline__ u64 ffma2(u64 a, u64 b, u64 c){
    u64 d; asm("fma.rn.f32x2 %0, %1, %2, %3;" : "=l"(d) : "l"(a), "l"(b), "l"(c)); return d;
}
__device__ __forceinline__ void unpack2(u64 v, float& lo, float& hi){
    asm("mov.b64 {%0, %1}, %2;" : "=f"(lo), "=f"(hi) : "l"(v));
}
__device__ __forceinline__ u64 pack2(float x, float y){
    u64 v; asm("mov.b64 %0, {%1, %2};" : "=l"(v) : "f"(x), "f"(y)); return v;
}
__device__ __forceinline__ float sigmoidf_(float x){ return __fdividef(1.0f, 1.0f + __expf(-x)); }
__device__ __forceinline__ float tanhf_(float x){ return 1.0f - __fdividef(2.0f, __expf(2.0f*x) + 1.0f); }

__device__ __forceinline__ u32 smem_u32(const void* p){
    u32 a; asm("{ .reg .u64 t; cvta.to.shared.u64 t, %1; cvt.u32.u64 %0, t; }" : "=r"(a) : "l"(p)); return a;
}
__device__ __forceinline__ void ldmA(u32 a, u32& r0, u32& r1, u32& r2, u32& r3){
    asm volatile("ldmatrix.sync.aligned.m8n8.x4.shared.b16 {%0,%1,%2,%3},[%4];"
                 : "=r"(r0),"=r"(r1),"=r"(r2),"=r"(r3) : "r"(a));
}
__device__ __forceinline__ void ldmB(u32 a, u32& r0, u32& r1){
    asm volatile("ldmatrix.sync.aligned.m8n8.x2.shared.b16 {%0,%1},[%2];"
                 : "=r"(r0),"=r"(r1) : "r"(a));
}
__device__ __forceinline__ void mma16816(float* d, u32 a0,u32 a1,u32 a2,u32 a3,u32 b0,u32 b1){
    asm volatile("mma.sync.aligned.m16n8k16.row.col.f32.bf16.bf16.f32 "
                 "{%0,%1,%2,%3},{%4,%5,%6,%7},{%8,%9},{%0,%1,%2,%3};"
                 : "+f"(d[0]),"+f"(d[1]),"+f"(d[2]),"+f"(d[3])
                 : "r"(a0),"r"(a1),"r"(a2),"r"(a3),"r"(b0),"r"(b1));
}

// ---------------- scratch ----------------
__device__ float g_xT[(size_t)Tsz * Isz * Bsz];
__device__ float g_WihT0[(size_t)Isz * G3];
__device__ float g_gi0[(size_t)Tsz * Bsz * G3];
__device__ float g_gi1[(size_t)Tsz * Bsz * G3];
__device__ __nv_bfloat16 g_WhhB0[2][(size_t)G3 * Hsz];   // hi, lo  [768][256]
__device__ __nv_bfloat16 g_WihB1[2][(size_t)G3 * Hsz];
__device__ __nv_bfloat16 g_WhhB1[2][(size_t)G3 * Hsz];
__device__ __nv_bfloat16 g_hB0[4][(size_t)Bsz * Hsz];    // [hi_p0,hi_p1,lo_p0,lo_p1]
__device__ __nv_bfloat16 g_hB1[4][(size_t)Bsz * Hsz];
__device__ float g_z[(size_t)Bsz * Hsz];
__device__ float g_q[Bsz * Ksz];
__device__ float g_e1[(size_t)Ksz * Bsz * E1sz];
__device__ float g_e2[(size_t)Ksz * Bsz * E2sz];
__device__ unsigned g_cnt0, g_gen0, g_cnt1, g_gen1;

__device__ __forceinline__ void grid_bar(unsigned* cnt, volatile unsigned* gen,
                                         unsigned target, unsigned nCTAm1){
    __syncthreads();
    if (threadIdx.x == 0){
        __threadfence();
        if (atomicAdd(cnt, 1u) == nCTAm1){
            atomicExch(cnt, 0u); __threadfence(); *gen = target;
        } else { while (*gen < target) { } }
        __threadfence();
    }
    __syncthreads();
}

// ---------------- fp32 -> bf16 hi/lo split ----------------
__global__ void __launch_bounds__(256) cvt_split(
    const float* __restrict__ in, __nv_bfloat16* __restrict__ hi,
    __nv_bfloat16* __restrict__ lo, int n)
{
    int i = blockIdx.x * 256 + threadIdx.x;
    if (i < n){
        float v = in[i];
        __nv_bfloat16 h = __float2bfloat16(v);
        hi[i] = h;
        lo[i] = __float2bfloat16(v - __bfloat162float(h));
    }
}

// ---------------- transpose (for gi0 inputs) ----------------
__global__ void __launch_bounds__(256) transpose_s(
    const float* __restrict__ in, size_t inRS, size_t inZ,
    float* __restrict__ out, size_t outRS, size_t outZ)
{
    in  += (size_t)blockIdx.z * inZ;
    out += (size_t)blockIdx.z * outZ;
    __shared__ float t[32][33];
    const int tx = threadIdx.x & 31, ty = threadIdx.x >> 5;
    const int r0 = blockIdx.y * 32, c0 = blockIdx.x * 32;
    #pragma unroll
    for (int i = 0; i < 4; i++)
        t[ty + 8*i][tx] = in[(size_t)(r0 + ty + 8*i) * inRS + c0 + tx];
    __syncthreads();
    #pragma unroll
    for (int i = 0; i < 4; i++)
        out[(size_t)(c0 + ty + 8*i) * outRS + r0 + tx] = t[tx][ty + 8*i];
}

// ---------------- TN GEMM for gi0 (proven) ----------------
__global__ void __launch_bounds__(256) gemm_tn(
    const float* __restrict__ AT, size_t aRowStride, size_t aBlkStride, int mBlk,
    const float* __restrict__ WT, int N, int K, float* __restrict__ C)
{
    extern __shared__ float sm[];
    float* As = sm;
    float* Bs = sm + 64 * 128;
    const int tid = threadIdx.x, w = tid >> 5, lane = tid & 31;
    const int m0 = blockIdx.x * 128, n0 = blockIdx.y * 64;
    const int jl = w * 8;
    const float* Abase = AT + (size_t)(m0 / mBlk) * aBlkStride + (m0 % mBlk);

    u64 acc[4][4];
    #pragma unroll
    for (int r = 0; r < 4; r++)
        #pragma unroll
        for (int q = 0; q < 4; q++) acc[r][q] = 0ull;

    for (int kk = 0; kk < K; kk += 64){
        __syncthreads();
        for (int i = tid; i < 64 * 32; i += 256){
            int k = i >> 5, q = i & 31;
            *reinterpret_cast<float4*>(As + k*128 + q*4) =
                *reinterpret_cast<const float4*>(Abase + (size_t)(kk+k)*aRowStride + q*4);
        }
        for (int i = tid; i < 64 * 16; i += 256){
            int k = i >> 4, q = i & 15;
            *reinterpret_cast<float4*>(Bs + k*64 + q*4) =
                *reinterpret_cast<const float4*>(WT + (size_t)(kk+k)*N + n0 + q*4);
        }
        __syncthreads();
        #pragma unroll 8
        for (int k = 0; k < 64; k++){
            U64x2 ap = *reinterpret_cast<const U64x2*>(As + k*128 + 4*lane);
            float f0,f1,f2,f3;
            unpack2(ap.lo, f0, f1); unpack2(ap.hi, f2, f3);
            u64 ad[4] = { pack2(f0,f0), pack2(f1,f1), pack2(f2,f2), pack2(f3,f3) };
            U64x2 b01 = *reinterpret_cast<const U64x2*>(Bs + k*64 + jl);
            U64x2 b23 = *reinterpret_cast<const U64x2*>(Bs + k*64 + jl + 4);
            u64 bq[4] = { b01.lo, b01.hi, b23.lo, b23.hi };
            #pragma unroll
            for (int r = 0; r < 4; r++)
                #pragma unroll
                for (int q = 0; q < 4; q++)
                    acc[r][q] = ffma2(ad[r], bq[q], acc[r][q]);
        }
    }
    #pragma unroll
    for (int r = 0; r < 4; r++){
        int row = m0 + 4*lane + r;
        float o[8];
        #pragma unroll
        for (int q = 0; q < 4; q++) unpack2(acc[r][q], o[2*q], o[2*q+1]);
        *reinterpret_cast<float4*>(C + (size_t)row*N + n0 + jl)     = make_float4(o[0],o[1],o[2],o[3]);
        *reinterpret_cast<float4*>(C + (size_t)row*N + n0 + jl + 4) = make_float4(o[4],o[5],o[6],o[7]);
    }
}

// ---------------------------------------------------------------------------
// Persistent tensor-core GRU layer. grid (16,8)=128 CTAs, 256 thr (8 warps:
// 2m x 4n; warp tile 32x24). CTA: 64 batch x 32 hidden (96 gate-cols,
// interleaved j = 3*hcol+g). B tiles bf16 smem-resident; A = h bf16 hi/lo
// published to gmem each step; h_own fp32 in registers.
// ---------------------------------------------------------------------------
#define SWZ(row, c) ((u32)((((c) ^ ((row) & 7)) << 4)))

__device__ __forceinline__ void mma_pass(float acc[2][3][4], char* Asm, char* Bsm,
                                         int lane, int wM, int wN){
    u32 aB = smem_u32(Asm), bB = smem_u32(Bsm);
    int ar0 = wM*32 + (lane & 15), ar1 = ar0 + 16;
    int ah = lane >> 4;
    int br = wN*24 + (lane & 7);
    int bh = (lane >> 3) & 1;
    #pragma unroll
    for (int kk = 0; kk < 16; kk++){
        u32 a0,a1,a2,a3,c0,c1,c2,c3;
        int ac = kk*2 + ah;
        ldmA(aB + (u32)ar0*512 + SWZ(ar0, ac), a0,a1,a2,a3);
        ldmA(aB + (u32)ar1*512 + SWZ(ar1, ac), c0,c1,c2,c3);
        #pragma unroll
        for (int f = 0; f < 3; f++){
            int brr = br + f*8;
            int bc = kk*2 + bh;
            u32 b0,b1;
            ldmB(bB + (u32)brr*512 + SWZ(brr, bc), b0,b1);
            mma16816(acc[0][f], a0,a1,a2,a3, b0,b1);
            mma16816(acc[1][f], c0,c1,c2,c3, b0,b1);
        }
    }
}

__device__ __forceinline__ void fill_A(char* Asm, const __nv_bfloat16* src, int m0, int tid){
    #pragma unroll
    for (int i = 0; i < 8; i++){
        int id = tid + i*256, row = id >> 5, c = id & 31;
        uint4 v = __ldcg(reinterpret_cast<const uint4*>(src + (size_t)(m0+row)*Hsz) + c);
        *reinterpret_cast<uint4*>(Asm + (size_t)row*512 + SWZ(row, c)) = v;
    }
}

__device__ __forceinline__ void fill_B(char* dst, const __nv_bfloat16* W, int n0, int tid){
    for (int i = tid; i < 96*32; i += 256){
        int j = i >> 5, c = i & 31;
        int wrow = (j % 3)*Hsz + n0 + (j/3);
        uint4 v = *(reinterpret_cast<const uint4*>(W + (size_t)wrow*Hsz) + c);
        *reinterpret_cast<uint4*>(dst + (size_t)j*512 + SWZ(j, c)) = v;
    }
}

__device__ __forceinline__ void zero_acc(float a[2][3][4]){
    #pragma unroll
    for (int m = 0; m < 2; m++)
        #pragma unroll
        for (int f = 0; f < 3; f++)
            #pragma unroll
            for (int q = 0; q < 4; q++) a[m][f][q] = 0.0f;
}

// store interleaved (gate-triple adjacent): col j as-is
__device__ __forceinline__ void store_gh(float* ghsm, float acc[2][3][4], int lane, int wM, int wN){
    #pragma unroll
    for (int m = 0; m < 2; m++)
        #pragma unroll
        for (int f = 0; f < 3; f++){
            int r0 = wM*32 + m*16 + (lane >> 2);
            int c0 = wN*24 + f*8 + 2*(lane & 3);
            *reinterpret_cast<float2*>(ghsm + r0*96 + c0)     = make_float2(acc[m][f][0], acc[m][f][1]);
            *reinterpret_cast<float2*>(ghsm + (r0+8)*96 + c0) = make_float2(acc[m][f][2], acc[m][f][3]);
        }
}

// store de-interleaved natural layout: j -> (j%3)*32 + j/3
__device__ __forceinline__ void store_nat(float* ghsm, float acc[2][3][4], int lane, int wM, int wN){
    #pragma unroll
    for (int m = 0; m < 2; m++)
        #pragma unroll
        for (int f = 0; f < 3; f++){
            int r0 = wM*32 + m*16 + (lane >> 2);
            int j0 = wN*24 + f*8 + 2*(lane & 3);
            int n0c = (j0 % 3)*32 + j0/3;
            int n1c = ((j0+1) % 3)*32 + (j0+1)/3;
            ghsm[r0*96 + n0c]     = acc[m][f][0];
            ghsm[r0*96 + n1c]     = acc[m][f][1];
            ghsm[(r0+8)*96 + n0c] = acc[m][f][2];
            ghsm[(r0+8)*96 + n1c] = acc[m][f][3];
        }
}

template<bool FUSE>
__global__ void __launch_bounds__(256) gru_mma(
    const __nv_bfloat16* __restrict__ WhhHi, const __nv_bfloat16* __restrict__ WhhLo,
    const __nv_bfloat16* __restrict__ WihHi, const __nv_bfloat16* __restrict__ WihLo,
    const float* __restrict__ giAll, const float* __restrict__ bih,
    const float* __restrict__ bhh, __nv_bfloat16* __restrict__ hB,
    float* __restrict__ gi1out, float* __restrict__ zout,
    unsigned* cnt, unsigned* genp)
{
    extern __shared__ char smc[];
    char* B_hh_hi = smc;
    char* B_hh_lo = smc + 48*1024;
    char* B_ih_hi = smc + 96*1024;
    char* B_ih_lo = smc + 144*1024;
    char* Asm     = smc + (FUSE ? 192 : 96)*1024;
    float* ghsm   = reinterpret_cast<float*>(Asm);     // reused after MMA

    const int tid = threadIdx.x, lane = tid & 31, w = tid >> 5;
    const int wM = w >> 2, wN = w & 3;
    const int m0 = blockIdx.x * 64, n0 = blockIdx.y * 32;
    const size_t PG = (size_t)Bsz * G3, PHB = (size_t)Bsz * Hsz;

    fill_B(B_hh_hi, WhhHi, n0, tid);
    fill_B(B_hh_lo, WhhLo, n0, tid);
    if constexpr (FUSE){
        fill_B(B_ih_hi, WihHi, n0, tid);
        fill_B(B_ih_lo, WihLo, n0, tid);
    }

    const int hcol = tid & 31, rb = (tid >> 5) * 8;
    float br_ = bih[0*Hsz + n0 + hcol], bz_ = bih[1*Hsz + n0 + hcol], bn_ = bih[2*Hsz + n0 + hcol];
    float cr_ = bhh[0*Hsz + n0 + hcol], cz_ = bhh[1*Hsz + n0 + hcol], cn_ = bhh[2*Hsz + n0 + hcol];
    float h_own[8];
    #pragma unroll
    for (int i = 0; i < 8; i++) h_own[i] = 0.0f;

    volatile unsigned* gen = genp;
    const unsigned gbase = *gen;
    __syncthreads();

    for (int t = 0; t < Tsz; t++){
        float accG[2][3][4], accI[2][3][4];
        zero_acc(accG);
        if constexpr (FUSE) zero_acc(accI);

        if (t > 0){
            int pp = (t - 1) & 1;
            fill_A(Asm, hB + (size_t)pp * PHB, m0, tid);          // hi
            __syncthreads();
            mma_pass(accG, Asm, B_hh_hi, lane, wM, wN);
            mma_pass(accG, Asm, B_hh_lo, lane, wM, wN);
            if constexpr (FUSE){
                mma_pass(accI, Asm, B_ih_hi, lane, wM, wN);
                mma_pass(accI, Asm, B_ih_lo, lane, wM, wN);
            }
            __syncthreads();
            fill_A(Asm, hB + (size_t)(2 + pp) * PHB, m0, tid);    // lo
            __syncthreads();
            mma_pass(accG, Asm, B_hh_hi, lane, wM, wN);
            if constexpr (FUSE) mma_pass(accI, Asm, B_ih_hi, lane, wM, wN);
            __syncthreads();
            store_gh(ghsm, accG, lane, wM, wN);
            __syncthreads();
        }

        // ---- epilogue ----
        {
            int pp = t & 1;
            __nv_bfloat16* hHiW = hB + (size_t)pp * PHB;
            __nv_bfloat16* hLoW = hB + (size_t)(2 + pp) * PHB;
            #pragma unroll
            for (int rr = 0; rr < 8; rr++){
                int row = rb + rr;
                float ghr = 0.0f, ghz = 0.0f, ghn = 0.0f;
                if (t > 0){
                    ghr = ghsm[row*96 + hcol*3 + 0];
                    ghz = ghsm[row*96 + hcol*3 + 1];
                    ghn = ghsm[row*96 + hcol*3 + 2];
                }
                const float* gp = giAll + (size_t)t*PG + (size_t)(m0+row)*G3 + n0 + hcol;
                float rg = sigmoidf_(gp[0]   + br_ + ghr + cr_);
                float zg = sigmoidf_(gp[256] + bz_ + ghz + cz_);
                float ng = tanhf_(gp[512] + bn_ + rg*(ghn + cn_));
                float hv = (1.0f - zg)*ng + zg*h_own[rr];
                h_own[rr] = hv;
                __nv_bfloat16 hh = __float2bfloat16(hv);
                size_t gidx = (size_t)(m0+row)*Hsz + n0 + hcol;
                hHiW[gidx] = hh;
                hLoW[gidx] = __float2bfloat16(hv - __bfloat162float(hh));
                if (!FUSE && t == Tsz-1) zout[gidx] = hv;
            }
        }

        if constexpr (FUSE){
            if (t > 0){
                __syncthreads();
                store_nat(ghsm, accI, lane, wM, wN);
                __syncthreads();
                float* go = gi1out + (size_t)(t-1)*PG;
                #pragma unroll
                for (int i = 0; i < 6; i++){
                    int fid = tid + i*256;
                    int row = fid / 24, cq = fid % 24;
                    int g = cq >> 3, hc4 = (cq & 7)*4;
                    float4 v = *reinterpret_cast<const float4*>(ghsm + row*96 + g*32 + hc4);
                    *reinterpret_cast<float4*>(go + (size_t)(m0+row)*G3 + g*256 + n0 + hc4) = v;
                }
            }
        }

        grid_bar(cnt, gen, gbase + (unsigned)t + 1u, 127u);
    }

    // ---- FUSE tail: gi1[127] = h[127] @ Wih1^T ----
    if constexpr (FUSE){
        float accI[2][3][4];
        zero_acc(accI);
        int pp = (Tsz - 1) & 1;
        fill_A(Asm, hB + (size_t)pp * PHB, m0, tid);
        __syncthreads();
        mma_pass(accI, Asm, B_ih_hi, lane, wM, wN);
        mma_pass(accI, Asm, B_ih_lo, lane, wM, wN);
        __syncthreads();
        fill_A(Asm, hB + (size_t)(2 + pp) * PHB, m0, tid);
        __syncthreads();
        mma_pass(accI, Asm, B_ih_hi, lane, wM, wN);
        __syncthreads();
        store_nat(ghsm, accI, lane, wM, wN);
        __syncthreads();
        float* go = gi1out + (size_t)(Tsz-1)*PG;
        #pragma unroll
        for (int i = 0; i < 6; i++){
            int fid = tid + i*256;
            int row = fid / 24, cq = fid % 24;
            int g = cq >> 3, hc4 = (cq & 7)*4;
            float4 v = *reinterpret_cast<const float4*>(ghsm + row*96 + g*32 + hc4);
            *reinterpret_cast<float4*>(go + (size_t)(m0+row)*G3 + g*256 + n0 + hc4) = v;
        }
    }
}

// ---------------- experts / q / combine (proven) ----------------
__global__ void __launch_bounds__(256) gemm_relu_kernel(
    const float* __restrict__ Abase, size_t aStride,
    const float* __restrict__ Wbase, size_t wStride,
    const float* __restrict__ biasBase, size_t bStride,
    float* __restrict__ Cbase, size_t cStride, int Kdim, int Ndim)
{
    const int e = blockIdx.z;
    const float* A = Abase + (size_t)e*aStride;
    const float* W = Wbase + (size_t)e*wStride;
    const float* bias = biasBase + (size_t)e*bStride;
    float* C = Cbase + (size_t)e*cStride;
    const int m0 = blockIdx.x*64, n0 = blockIdx.y*64;
    const int tid = threadIdx.x, tx = tid & 15, ty = tid >> 4;
    __shared__ float2 As[32][64];
    __shared__ float  Ws[32][64];
    u64 acc[4][2];
    #pragma unroll
    for (int r = 0; r < 4; r++){ acc[r][0] = 0ull; acc[r][1] = 0ull; }
    for (int kk = 0; kk < Kdim; kk += 32){
        __syncthreads();
        {
            int row = tid >> 2;
            const float* ar = A + (size_t)(m0+row)*Kdim + kk;
            const float* wr = W + (size_t)(n0+row)*Kdim + kk;
            #pragma unroll
            for (int hh = 0; hh < 2; hh++){
                int kb = ((tid & 3) << 2) + (hh << 4);
                float4 va = *reinterpret_cast<const float4*>(ar + kb);
                As[kb+0][row] = make_float2(va.x, va.x);
                As[kb+1][row] = make_float2(va.y, va.y);
                As[kb+2][row] = make_float2(va.z, va.z);
                As[kb+3][row] = make_float2(va.w, va.w);
                float4 vw = *reinterpret_cast<const float4*>(wr + kb);
                Ws[kb+0][row] = vw.x; Ws[kb+1][row] = vw.y;
                Ws[kb+2][row] = vw.z; Ws[kb+3][row] = vw.w;
            }
        }
        __syncthreads();
        #pragma unroll 8
        for (int k = 0; k < 32; k++){
            u64 b0 = *reinterpret_cast<const u64*>(&Ws[k][tx << 1]);
            u64 b1 = *reinterpret_cast<const u64*>(&Ws[k][(tx << 1) + 32]);
            #pragma unroll
            for (int r = 0; r < 4; r++){
                u64 a = *reinterpret_cast<const u64*>(&As[k][(ty << 2) + r]);
                acc[r][0] = ffma2(a, b0, acc[r][0]);
                acc[r][1] = ffma2(a, b1, acc[r][1]);
            }
        }
    }
    #pragma unroll
    for (int r = 0; r < 4; r++){
        int row = m0 + (ty << 2) + r;
        #pragma unroll
        for (int p = 0; p < 2; p++){
            int j = (tx << 1) + (p << 5);
            float c0, c1;
            unpack2(acc[r][p], c0, c1);
            c0 = fmaxf(c0 + bias[n0+j],   0.0f);
            c1 = fmaxf(c1 + bias[n0+j+1], 0.0f);
            *reinterpret_cast<float2*>(&C[(size_t)row*Ndim + n0 + j]) = make_float2(c0, c1);
        }
    }
}

__global__ void __launch_bounds__(256) qkernel(
    const float* __restrict__ z, const float* __restrict__ cent, float* __restrict__ q)
{
    int warp = threadIdx.x >> 5, lane = threadIdx.x & 31;
    int b = blockIdx.x*8 + warp;
    float zr[8];
    #pragma unroll
    for (int i = 0; i < 8; i++) zr[i] = z[(size_t)b*Hsz + lane + 32*i];
    float s = 0.0f;
    for (int k = 0; k < Ksz; k++){
        float d = 0.0f;
        #pragma unroll
        for (int i = 0; i < 8; i++){
            float t = zr[i] - cent[k*Hsz + lane + 32*i];
            d = fmaf(t, t, d);
        }
        #pragma unroll
        for (int off = 16; off; off >>= 1) d += __shfl_xor_sync(0xffffffffu, d, off);
        if (lane == k) s = 1.0f / (1.0f + d);
    }
    float tot = s;
    #pragma unroll
    for (int off = 16; off; off >>= 1) tot += __shfl_xor_sync(0xffffffffu, tot, off);
    if (lane < Ksz) q[(size_t)b*Ksz + lane] = s / tot;
}

__global__ void __launch_bounds__(256) combine_kernel(
    const float* __restrict__ h2, const float* __restrict__ q,
    const float* __restrict__ eW3, const float* __restrict__ eb3, float* __restrict__ out)
{
    int warp = threadIdx.x >> 5, lane = threadIdx.x & 31;
    int b = blockIdx.x*8 + warp;
    float acc[Ksz][2];
    #pragma unroll
    for (int k = 0; k < Ksz; k++){ acc[k][0] = 0.0f; acc[k][1] = 0.0f; }
    for (int f = lane; f < E2sz; f += 32){
        #pragma unroll
        for (int k = 0; k < Ksz; k++){
            float hv = h2[((size_t)k*Bsz + b)*E2sz + f];
            acc[k][0] = fmaf(hv, eW3[(size_t)(k*2+0)*E2sz + f], acc[k][0]);
            acc[k][1] = fmaf(hv, eW3[(size_t)(k*2+1)*E2sz + f], acc[k][1]);
        }
    }
    #pragma unroll
    for (int k = 0; k < Ksz; k++)
        #pragma unroll
        for (int c = 0; c < 2; c++)
            #pragma unroll
            for (int off = 16; off; off >>= 1)
                acc[k][c] += __shfl_xor_sync(0xffffffffu, acc[k][c], off);
    if (lane == 0){
        float p0 = 0.0f, p1 = 0.0f;
        #pragma unroll
        for (int k = 0; k < Ksz; k++){
            float qq = q[(size_t)b*Ksz + k];
            p0 = fmaf(qq, acc[k][0] + eb3[k*2+0], p0);
            p1 = fmaf(qq, acc[k][1] + eb3[k*2+1], p1);
        }
        out[b*2+0] = p0; out[b*2+1] = p1;
    }
}

// ---------------------------------------------------------------------------
#define MMA_SMEM_FUSE  ((192 + 32) * 1024)
#define MMA_SMEM_PLAIN ((96 + 32) * 1024)
#define GEMM_SMEM      ((64*128 + 64*64) * 4)

extern "C" void kernel_launch(void* const* d_in, const int* in_sizes, int n_in,
                              void* d_out, int out_size)
{
    const float* x    = (const float*)d_in[0];
    const float* Wih0 = (const float*)d_in[1];
    const float* Whh0 = (const float*)d_in[2];
    const float* bih0 = (const float*)d_in[3];
    const float* bhh0 = (const float*)d_in[4];
    const float* Wih1 = (const float*)d_in[5];
    const float* Whh1 = (const float*)d_in[6];
    const float* bih1 = (const float*)d_in[7];
    const float* bhh1 = (const float*)d_in[8];
    const float* cent = (const float*)d_in[9];
    const float* eW1  = (const float*)d_in[10];
    const float* eb1  = (const float*)d_in[11];
    const float* eW2  = (const float*)d_in[12];
    const float* eb2  = (const float*)d_in[13];
    const float* eW3  = (const float*)d_in[14];
    const float* eb3  = (const float*)d_in[15];
    float* out = (float*)d_out;

    float *xT, *WihT0, *gi0, *gi1, *z, *qb, *e1, *e2;
    __nv_bfloat16 *whhB0, *wihB1, *whhB1, *hB0, *hB1;
    unsigned *cnt0, *gen0, *cnt1, *gen1;
    cudaGetSymbolAddress((void**)&xT,    g_xT);
    cudaGetSymbolAddress((void**)&WihT0, g_WihT0);
    cudaGetSymbolAddress((void**)&gi0,   g_gi0);
    cudaGetSymbolAddress((void**)&gi1,   g_gi1);
    cudaGetSymbolAddress((void**)&whhB0, g_WhhB0);
    cudaGetSymbolAddress((void**)&wihB1, g_WihB1);
    cudaGetSymbolAddress((void**)&whhB1, g_WhhB1);
    cudaGetSymbolAddress((void**)&hB0,   g_hB0);
    cudaGetSymbolAddress((void**)&hB1,   g_hB1);
    cudaGetSymbolAddress((void**)&z,     g_z);
    cudaGetSymbolAddress((void**)&qb,    g_q);
    cudaGetSymbolAddress((void**)&e1,    g_e1);
    cudaGetSymbolAddress((void**)&e2,    g_e2);
    cudaGetSymbolAddress((void**)&cnt0,  g_cnt0);
    cudaGetSymbolAddress((void**)&gen0,  g_gen0);
    cudaGetSymbolAddress((void**)&cnt1,  g_cnt1);
    cudaGetSymbolAddress((void**)&gen1,  g_gen1);

    cudaFuncSetAttribute(gru_mma<true>,
                         cudaFuncAttributeMaxDynamicSharedMemorySize, MMA_SMEM_FUSE);
    cudaFuncSetAttribute(gru_mma<false>,
                         cudaFuncAttributeMaxDynamicSharedMemorySize, MMA_SMEM_PLAIN);
    cudaFuncSetAttribute(gemm_tn,
                         cudaFuncAttributeMaxDynamicSharedMemorySize, GEMM_SMEM);

    const size_t WN = (size_t)G3 * Hsz;

    // ---- layout transforms + weight splits ----
    transpose_s<<<dim3(4, 32, 128), 256>>>(x, (size_t)Tsz*Isz, (size_t)Isz,
                                           xT, (size_t)Bsz, (size_t)Isz*Bsz);
    transpose_s<<<dim3(4, 24, 1), 256>>>(Wih0, Isz, 0, WihT0, G3, 0);
    cvt_split<<<(int)(WN/256), 256>>>(Whh0, whhB0, whhB0 + WN, (int)WN);
    cvt_split<<<(int)(WN/256), 256>>>(Wih1, wihB1, wihB1 + WN, (int)WN);
    cvt_split<<<(int)(WN/256), 256>>>(Whh1, whhB1, whhB1 + WN, (int)WN);

    // ---- gi0 = x @ Wih0^T ----
    gemm_tn<<<dim3(1024, 12), 256, GEMM_SMEM>>>(
        xT, (size_t)Bsz, (size_t)Isz*Bsz, Bsz, WihT0, G3, Isz, gi0);

    // ---- layer 0 persistent tensor chain (emits gi1) ----
    gru_mma<true><<<dim3(16, 8), 256, MMA_SMEM_FUSE>>>(
        whhB0, whhB0 + WN, wihB1, wihB1 + WN, gi0, bih0, bhh0,
        hB0, gi1, nullptr, cnt0, gen0);

    // ---- layer 1 persistent tensor chain (emits z) ----
    gru_mma<false><<<dim3(16, 8), 256, MMA_SMEM_PLAIN>>>(
        whhB1, whhB1 + WN, nullptr, nullptr, gi1, bih1, bhh1,
        hB1, nullptr, z, cnt1, gen1);

    // ---- clustering + experts + combine ----
    qkernel<<<128, 256>>>(z, cent, qb);
    gemm_relu_kernel<<<dim3(16, 8, 8), 256>>>(
        z, (size_t)0, eW1, (size_t)E1sz*Hsz, eb1, (size_t)E1sz,
        e1, (size_t)Bsz*E1sz, Hsz, E1sz);
    gemm_relu_kernel<<<dim3(16, 4, 8), 256>>>(
        e1, (size_t)Bsz*E1sz, eW2, (size_t)E2sz*E1sz, eb2, (size_t)E2sz,
        e2, (size_t)Bsz*E2sz, E1sz, E2sz);
    combine_kernel<<<128, 256>>>(e2, qb, eW3, eb3, out);

    (void)in_sizes; (void)n_in; (void)out_size;
}

// round 10
// speedup vs baseline: 2.0179x; 1.0758x over previous
#include <cuda_runtime.h>
#include <cuda_bf16.h>
#include <cstddef>

#define Bsz  1024
#define Tsz  128
#define Isz  128
#define Hsz  256
#define G3   768
#define Ksz  8
#define E1sz 512
#define E2sz 256
#define MT   (Bsz * Tsz)

typedef unsigned long long u64;
typedef unsigned int u32;

__device__ __forceinline__ u64 ffma2(u64 a, u64 b, u64 c){
    u64 d; asm("fma.rn.f32x2 %0, %1, %2, %3;" : "=l"(d) : "l"(a), "l"(b), "l"(c)); return d;
}
__device__ __forceinline__ void unpack2(u64 v, float& lo, float& hi){
    asm("mov.b64 {%0, %1}, %2;" : "=f"(lo), "=f"(hi) : "l"(v));
}
__device__ __forceinline__ float sigmoidf_(float x){ return __fdividef(1.0f, 1.0f + __expf(-x)); }
__device__ __forceinline__ float tanhf_(float x){ return 1.0f - __fdividef(2.0f, __expf(2.0f*x) + 1.0f); }

__device__ __forceinline__ u32 smem_u32(const void* p){
    u32 a; asm("{ .reg .u64 t; cvta.to.shared.u64 t, %1; cvt.u32.u64 %0, t; }" : "=r"(a) : "l"(p)); return a;
}
__device__ __forceinline__ void ldmA(u32 a, u32& r0, u32& r1, u32& r2, u32& r3){
    asm volatile("ldmatrix.sync.aligned.m8n8.x4.shared.b16 {%0,%1,%2,%3},[%4];"
                 : "=r"(r0),"=r"(r1),"=r"(r2),"=r"(r3) : "r"(a));
}
__device__ __forceinline__ void ldmB(u32 a, u32& r0, u32& r1){
    asm volatile("ldmatrix.sync.aligned.m8n8.x2.shared.b16 {%0,%1},[%2];"
                 : "=r"(r0),"=r"(r1) : "r"(a));
}
__device__ __forceinline__ void mma16816(float* d, u32 a0,u32 a1,u32 a2,u32 a3,u32 b0,u32 b1){
    asm volatile("mma.sync.aligned.m16n8k16.row.col.f32.bf16.bf16.f32 "
                 "{%0,%1,%2,%3},{%4,%5,%6,%7},{%8,%9},{%0,%1,%2,%3};"
                 : "+f"(d[0]),"+f"(d[1]),"+f"(d[2]),"+f"(d[3])
                 : "r"(a0),"r"(a1),"r"(a2),"r"(a3),"r"(b0),"r"(b1));
}

#define SWZ(row, c) ((u32)((((c) ^ ((row) & 7)) << 4)))

// ---------------- scratch ----------------
__device__ float g_gi0[(size_t)Tsz * Bsz * G3];
__device__ float g_gi1[(size_t)Tsz * Bsz * G3];
__device__ __nv_bfloat16 g_xB[2][(size_t)MT * Isz];      // x hi, lo
__device__ __nv_bfloat16 g_WihB0[2][(size_t)G3 * Isz];
__device__ __nv_bfloat16 g_WhhB0[2][(size_t)G3 * Hsz];
__device__ __nv_bfloat16 g_WihB1[2][(size_t)G3 * Hsz];
__device__ __nv_bfloat16 g_WhhB1[2][(size_t)G3 * Hsz];
__device__ __nv_bfloat16 g_hB0[4][(size_t)Bsz * Hsz];    // [hi_p0,hi_p1,lo_p0,lo_p1]
__device__ __nv_bfloat16 g_hB1[4][(size_t)Bsz * Hsz];
__device__ float g_z[(size_t)Bsz * Hsz];
__device__ float g_q[Bsz * Ksz];
__device__ float g_e1[(size_t)Ksz * Bsz * E1sz];
__device__ float g_e2[(size_t)Ksz * Bsz * E2sz];
__device__ unsigned g_cnt0, g_gen0, g_cnt1, g_gen1;

__device__ __forceinline__ void grid_bar(unsigned* cnt, volatile unsigned* gen,
                                         unsigned target, unsigned nCTAm1){
    __syncthreads();
    if (threadIdx.x == 0){
        __threadfence();
        if (atomicAdd(cnt, 1u) == nCTAm1){
            atomicExch(cnt, 0u); __threadfence(); *gen = target;
        } else { while (*gen < target) { } }
        __threadfence();
    }
    __syncthreads();
}

__global__ void __launch_bounds__(256) cvt_split(
    const float* __restrict__ in, __nv_bfloat16* __restrict__ hi,
    __nv_bfloat16* __restrict__ lo, int n)
{
    int i = blockIdx.x * 256 + threadIdx.x;
    if (i < n){
        float v = in[i];
        __nv_bfloat16 h = __float2bfloat16(v);
        hi[i] = h;
        lo[i] = __float2bfloat16(v - __bfloat162float(h));
    }
}

// ---------------------------------------------------------------------------
// mma_multi: load A frags once per k-chunk, feed up to 4 B operands.
// RS = smem row stride in bytes (512 for K=256 tiles, 256 for K=128).
// ---------------------------------------------------------------------------
template<int NOPS, int KK, int RS>
__device__ __forceinline__ void mma_multi(
    char* Asm,
    char* B0, float (&o0)[2][3][4], char* B1, float (&o1)[2][3][4],
    char* B2, float (&o2)[2][3][4], char* B3, float (&o3)[2][3][4],
    int lane, int wM, int wN)
{
    u32 aB = smem_u32(Asm);
    u32 bA0 = smem_u32(B0);
    u32 bA1 = (NOPS > 1) ? smem_u32(B1) : 0;
    u32 bA2 = (NOPS > 2) ? smem_u32(B2) : 0;
    u32 bA3 = (NOPS > 3) ? smem_u32(B3) : 0;
    const int ar0 = wM*32 + (lane & 15), ar1 = ar0 + 16;
    const int ah = lane >> 4;
    const int br = wN*24 + (lane & 7);
    const int bh = (lane >> 3) & 1;
    #pragma unroll
    for (int kk = 0; kk < KK; kk++){
        int ac = kk*2 + ah, bc = kk*2 + bh;
        u32 x0,x1,x2,x3, y0,y1,y2,y3;
        ldmA(aB + (u32)(ar0*RS) + SWZ(ar0, ac), x0,x1,x2,x3);
        ldmA(aB + (u32)(ar1*RS) + SWZ(ar1, ac), y0,y1,y2,y3);
        #pragma unroll
        for (int f = 0; f < 3; f++){
            int brr = br + f*8;
            u32 b0,b1;
            ldmB(bA0 + (u32)(brr*RS) + SWZ(brr, bc), b0,b1);
            mma16816(o0[0][f], x0,x1,x2,x3, b0,b1);
            mma16816(o0[1][f], y0,y1,y2,y3, b0,b1);
            if (NOPS > 1){
                ldmB(bA1 + (u32)(brr*RS) + SWZ(brr, bc), b0,b1);
                mma16816(o1[0][f], x0,x1,x2,x3, b0,b1);
                mma16816(o1[1][f], y0,y1,y2,y3, b0,b1);
            }
            if (NOPS > 2){
                ldmB(bA2 + (u32)(brr*RS) + SWZ(brr, bc), b0,b1);
                mma16816(o2[0][f], x0,x1,x2,x3, b0,b1);
                mma16816(o2[1][f], y0,y1,y2,y3, b0,b1);
            }
            if (NOPS > 3){
                ldmB(bA3 + (u32)(brr*RS) + SWZ(brr, bc), b0,b1);
                mma16816(o3[0][f], x0,x1,x2,x3, b0,b1);
                mma16816(o3[1][f], y0,y1,y2,y3, b0,b1);
            }
        }
    }
}

__device__ __forceinline__ void fill_A(char* Asm, const __nv_bfloat16* src, int m0, int tid){
    #pragma unroll
    for (int i = 0; i < 8; i++){
        int id = tid + i*256, row = id >> 5, c = id & 31;
        uint4 v = __ldcg(reinterpret_cast<const uint4*>(src + (size_t)(m0+row)*Hsz) + c);
        *reinterpret_cast<uint4*>(Asm + (size_t)row*512 + SWZ(row, c)) = v;
    }
}
__device__ __forceinline__ void pf_A(uint4 pf[8], const __nv_bfloat16* src, int m0, int tid){
    #pragma unroll
    for (int i = 0; i < 8; i++){
        int id = tid + i*256, row = id >> 5, c = id & 31;
        pf[i] = __ldcg(reinterpret_cast<const uint4*>(src + (size_t)(m0+row)*Hsz) + c);
    }
}
__device__ __forceinline__ void st_A(char* Asm, const uint4 pf[8], int tid){
    #pragma unroll
    for (int i = 0; i < 8; i++){
        int id = tid + i*256, row = id >> 5, c = id & 31;
        *reinterpret_cast<uint4*>(Asm + (size_t)row*512 + SWZ(row, c)) = pf[i];
    }
}
__device__ __forceinline__ void fill_B(char* dst, const __nv_bfloat16* W, int n0, int tid){
    for (int i = tid; i < 96*32; i += 256){
        int j = i >> 5, c = i & 31;
        int wrow = (j % 3)*Hsz + n0 + (j/3);
        uint4 v = *(reinterpret_cast<const uint4*>(W + (size_t)wrow*Hsz) + c);
        *reinterpret_cast<uint4*>(dst + (size_t)j*512 + SWZ(j, c)) = v;
    }
}
__device__ __forceinline__ void zero_acc(float a[2][3][4]){
    #pragma unroll
    for (int m = 0; m < 2; m++)
        #pragma unroll
        for (int f = 0; f < 3; f++)
            #pragma unroll
            for (int q = 0; q < 4; q++) a[m][f][q] = 0.0f;
}
// interleaved gh store: col j = 3*h+g as-is
__device__ __forceinline__ void store_gh(float* ghsm, float acc[2][3][4], int lane, int wM, int wN){
    #pragma unroll
    for (int m = 0; m < 2; m++)
        #pragma unroll
        for (int f = 0; f < 3; f++){
            int r0 = wM*32 + m*16 + (lane >> 2);
            int c0 = wN*24 + f*8 + 2*(lane & 3);
            *reinterpret_cast<float2*>(ghsm + r0*96 + c0)     = make_float2(acc[m][f][0], acc[m][f][1]);
            *reinterpret_cast<float2*>(ghsm + (r0+8)*96 + c0) = make_float2(acc[m][f][2], acc[m][f][3]);
        }
}
// de-interleaved natural store: j -> (j%3)*32 + j/3
__device__ __forceinline__ void store_nat(float* ghsm, float acc[2][3][4], int lane, int wM, int wN){
    #pragma unroll
    for (int m = 0; m < 2; m++)
        #pragma unroll
        for (int f = 0; f < 3; f++){
            int r0 = wM*32 + m*16 + (lane >> 2);
            int j0 = wN*24 + f*8 + 2*(lane & 3);
            int n0c = (j0 % 3)*32 + j0/3;
            int n1c = ((j0+1) % 3)*32 + (j0+1)/3;
            ghsm[r0*96 + n0c]     = acc[m][f][0];
            ghsm[r0*96 + n1c]     = acc[m][f][1];
            ghsm[(r0+8)*96 + n0c] = acc[m][f][2];
            ghsm[(r0+8)*96 + n1c] = acc[m][f][3];
        }
}

// ---------------------------------------------------------------------------
// gi0 = x @ Wih0^T via bf16 MMA 3-pass. Grid (8 n-blocks, 2048 m-blocks).
// CTA: 64 m-rows x 96 gate-cols, K=128 (RS=256). smem 104KB -> 2 CTA/SM.
// ---------------------------------------------------------------------------
__global__ void __launch_bounds__(256) gi0_mma(
    const __nv_bfloat16* __restrict__ xHi, const __nv_bfloat16* __restrict__ xLo,
    const __nv_bfloat16* __restrict__ wHi, const __nv_bfloat16* __restrict__ wLo,
    float* __restrict__ gi0)
{
    extern __shared__ char smc[];
    char* Bhi = smc;                 // 24KB
    char* Blo = smc + 24*1024;       // 24KB
    char* Ahi = smc + 48*1024;       // 16KB
    char* Alo = smc + 64*1024;       // 16KB
    float* ghsm = reinterpret_cast<float*>(smc + 48*1024);  // 24KB, reused post-MMA

    const int tid = threadIdx.x, lane = tid & 31, w = tid >> 5;
    const int wM = w >> 2, wN = w & 3;
    const int n0 = blockIdx.x * 32, m0 = blockIdx.y * 64;
    const size_t PG = (size_t)Bsz * G3;

    // B fill: 96 rows x 16 chunks
    for (int i = tid; i < 96*16; i += 256){
        int j = i >> 4, c = i & 15;
        int wrow = (j % 3)*Hsz + n0 + (j/3);
        *reinterpret_cast<uint4*>(Bhi + (size_t)j*256 + SWZ(j, c)) =
            *(reinterpret_cast<const uint4*>(wHi + (size_t)wrow*Isz) + c);
        *reinterpret_cast<uint4*>(Blo + (size_t)j*256 + SWZ(j, c)) =
            *(reinterpret_cast<const uint4*>(wLo + (size_t)wrow*Isz) + c);
    }
    // A fill: 64 rows x 16 chunks
    #pragma unroll
    for (int i = 0; i < 4; i++){
        int id = tid + i*256, row = id >> 4, c = id & 15;
        *reinterpret_cast<uint4*>(Ahi + (size_t)row*256 + SWZ(row, c)) =
            *(reinterpret_cast<const uint4*>(xHi + (size_t)(m0+row)*Isz) + c);
        *reinterpret_cast<uint4*>(Alo + (size_t)row*256 + SWZ(row, c)) =
            *(reinterpret_cast<const uint4*>(xLo + (size_t)(m0+row)*Isz) + c);
    }
    __syncthreads();

    float acc[2][3][4];
    zero_acc(acc);
    mma_multi<2, 8, 256>(Ahi, Bhi, acc, Blo, acc, Bhi, acc, Bhi, acc, lane, wM, wN);
    mma_multi<1, 8, 256>(Alo, Bhi, acc, Bhi, acc, Bhi, acc, Bhi, acc, lane, wM, wN);
    __syncthreads();
    store_nat(ghsm, acc, lane, wM, wN);
    __syncthreads();

    const int b = m0 >> 7, t0 = m0 & 127;
    #pragma unroll
    for (int i = 0; i < 6; i++){
        int fid = tid + i*256;
        int row = fid / 24, cq = fid % 24;
        int g = cq >> 3, hc4 = (cq & 7)*4;
        float4 v = *reinterpret_cast<const float4*>(ghsm + row*96 + g*32 + hc4);
        *reinterpret_cast<float4*>(gi0 + (size_t)(t0+row)*PG + (size_t)b*G3 + g*256 + n0 + hc4) = v;
    }
}

// ---------------------------------------------------------------------------
// Persistent tensor-core GRU layer (proven R9 skeleton + mma_multi + A-prefetch)
// ---------------------------------------------------------------------------
template<bool FUSE>
__global__ void __launch_bounds__(256) gru_mma(
    const __nv_bfloat16* __restrict__ WhhHi, const __nv_bfloat16* __restrict__ WhhLo,
    const __nv_bfloat16* __restrict__ WihHi, const __nv_bfloat16* __restrict__ WihLo,
    const float* __restrict__ giAll, const float* __restrict__ bih,
    const float* __restrict__ bhh, __nv_bfloat16* __restrict__ hB,
    float* __restrict__ gi1out, float* __restrict__ zout,
    unsigned* cnt, unsigned* genp)
{
    extern __shared__ char smc[];
    char* B_hh_hi = smc;
    char* B_hh_lo = smc + 48*1024;
    char* B_ih_hi = smc + 96*1024;
    char* B_ih_lo = smc + 144*1024;
    char* Asm     = smc + (FUSE ? 192 : 96)*1024;
    float* ghsm   = reinterpret_cast<float*>(Asm);

    const int tid = threadIdx.x, lane = tid & 31, w = tid >> 5;
    const int wM = w >> 2, wN = w & 3;
    const int m0 = blockIdx.x * 64, n0 = blockIdx.y * 32;
    const size_t PG = (size_t)Bsz * G3, PHB = (size_t)Bsz * Hsz;

    fill_B(B_hh_hi, WhhHi, n0, tid);
    fill_B(B_hh_lo, WhhLo, n0, tid);
    if constexpr (FUSE){
        fill_B(B_ih_hi, WihHi, n0, tid);
        fill_B(B_ih_lo, WihLo, n0, tid);
    }

    const int hcol = tid & 31, rb = (tid >> 5) * 8;
    float br_ = bih[0*Hsz + n0 + hcol], bz_ = bih[1*Hsz + n0 + hcol], bn_ = bih[2*Hsz + n0 + hcol];
    float cr_ = bhh[0*Hsz + n0 + hcol], cz_ = bhh[1*Hsz + n0 + hcol], cn_ = bhh[2*Hsz + n0 + hcol];
    float h_own[8];
    #pragma unroll
    for (int i = 0; i < 8; i++) h_own[i] = 0.0f;

    volatile unsigned* gen = genp;
    const unsigned gbase = *gen;
    __syncthreads();

    for (int t = 0; t < Tsz; t++){
        float accG[2][3][4], accI[2][3][4];
        zero_acc(accG);
        if constexpr (FUSE) zero_acc(accI);

        if (t > 0){
            int pp = (t - 1) & 1;
            uint4 pf[8];
            pf_A(pf, hB + (size_t)(2 + pp) * PHB, m0, tid);       // prefetch lo
            fill_A(Asm, hB + (size_t)pp * PHB, m0, tid);          // hi
            __syncthreads();
            if constexpr (FUSE)
                mma_multi<4,16,512>(Asm, B_hh_hi, accG, B_hh_lo, accG,
                                    B_ih_hi, accI, B_ih_lo, accI, lane, wM, wN);
            else
                mma_multi<2,16,512>(Asm, B_hh_hi, accG, B_hh_lo, accG,
                                    B_hh_hi, accG, B_hh_hi, accG, lane, wM, wN);
            __syncthreads();
            st_A(Asm, pf, tid);                                   // lo
            __syncthreads();
            if constexpr (FUSE)
                mma_multi<2,16,512>(Asm, B_hh_hi, accG, B_ih_hi, accI,
                                    B_hh_hi, accG, B_hh_hi, accG, lane, wM, wN);
            else
                mma_multi<1,16,512>(Asm, B_hh_hi, accG, B_hh_hi, accG,
                                    B_hh_hi, accG, B_hh_hi, accG, lane, wM, wN);
            __syncthreads();
            store_gh(ghsm, accG, lane, wM, wN);
            __syncthreads();
        }

        // ---- epilogue ----
        {
            int pp = t & 1;
            __nv_bfloat16* hHiW = hB + (size_t)pp * PHB;
            __nv_bfloat16* hLoW = hB + (size_t)(2 + pp) * PHB;
            #pragma unroll
            for (int rr = 0; rr < 8; rr++){
                int row = rb + rr;
                float ghr = 0.0f, ghz = 0.0f, ghn = 0.0f;
                if (t > 0){
                    ghr = ghsm[row*96 + hcol*3 + 0];
                    ghz = ghsm[row*96 + hcol*3 + 1];
                    ghn = ghsm[row*96 + hcol*3 + 2];
                }
                const float* gp = giAll + (size_t)t*PG + (size_t)(m0+row)*G3 + n0 + hcol;
                float rg = sigmoidf_(gp[0]   + br_ + ghr + cr_);
                float zg = sigmoidf_(gp[256] + bz_ + ghz + cz_);
                float ng = tanhf_(gp[512] + bn_ + rg*(ghn + cn_));
                float hv = (1.0f - zg)*ng + zg*h_own[rr];
                h_own[rr] = hv;
                __nv_bfloat16 hh = __float2bfloat16(hv);
                size_t gidx = (size_t)(m0+row)*Hsz + n0 + hcol;
                hHiW[gidx] = hh;
                hLoW[gidx] = __float2bfloat16(hv - __bfloat162float(hh));
                if (!FUSE && t == Tsz-1) zout[gidx] = hv;
            }
        }

        if constexpr (FUSE){
            if (t > 0){
                __syncthreads();
                store_nat(ghsm, accI, lane, wM, wN);
                __syncthreads();
                float* go = gi1out + (size_t)(t-1)*PG;
                #pragma unroll
                for (int i = 0; i < 6; i++){
                    int fid = tid + i*256;
                    int row = fid / 24, cq = fid % 24;
                    int g = cq >> 3, hc4 = (cq & 7)*4;
                    float4 v = *reinterpret_cast<const float4*>(ghsm + row*96 + g*32 + hc4);
                    *reinterpret_cast<float4*>(go + (size_t)(m0+row)*G3 + g*256 + n0 + hc4) = v;
                }
            }
        }

        grid_bar(cnt, gen, gbase + (unsigned)t + 1u, 127u);
    }

    // ---- FUSE tail: gi1[127] ----
    if constexpr (FUSE){
        float accI[2][3][4];
        zero_acc(accI);
        int pp = (Tsz - 1) & 1;
        uint4 pf[8];
        pf_A(pf, hB + (size_t)(2 + pp) * PHB, m0, tid);
        fill_A(Asm, hB + (size_t)pp * PHB, m0, tid);
        __syncthreads();
        mma_multi<2,16,512>(Asm, B_ih_hi, accI, B_ih_lo, accI,
                            B_ih_hi, accI, B_ih_hi, accI, lane, wM, wN);
        __syncthreads();
        st_A(Asm, pf, tid);
        __syncthreads();
        mma_multi<1,16,512>(Asm, B_ih_hi, accI, B_ih_hi, accI,
                            B_ih_hi, accI, B_ih_hi, accI, lane, wM, wN);
        __syncthreads();
        store_nat(ghsm, accI, lane, wM, wN);
        __syncthreads();
        float* go = gi1out + (size_t)(Tsz-1)*PG;
        #pragma unroll
        for (int i = 0; i < 6; i++){
            int fid = tid + i*256;
            int row = fid / 24, cq = fid % 24;
            int g = cq >> 3, hc4 = (cq & 7)*4;
            float4 v = *reinterpret_cast<const float4*>(ghsm + row*96 + g*32 + hc4);
            *reinterpret_cast<float4*>(go + (size_t)(m0+row)*G3 + g*256 + n0 + hc4) = v;
        }
    }
}

// ---------------- experts / q / combine (proven) ----------------
__global__ void __launch_bounds__(256) gemm_relu_kernel(
    const float* __restrict__ Abase, size_t aStride,
    const float* __restrict__ Wbase, size_t wStride,
    const float* __restrict__ biasBase, size_t bStride,
    float* __restrict__ Cbase, size_t cStride, int Kdim, int Ndim)
{
    typedef unsigned long long uu;
    const int e = blockIdx.z;
    const float* A = Abase + (size_t)e*aStride;
    const float* W = Wbase + (size_t)e*wStride;
    const float* bias = biasBase + (size_t)e*bStride;
    float* C = Cbase + (size_t)e*cStride;
    const int m0 = blockIdx.x*64, n0 = blockIdx.y*64;
    const int tid = threadIdx.x, tx = tid & 15, ty = tid >> 4;
    __shared__ float2 As[32][64];
    __shared__ float  Ws[32][64];
    uu acc[4][2];
    #pragma unroll
    for (int r = 0; r < 4; r++){ acc[r][0] = 0ull; acc[r][1] = 0ull; }
    for (int kk = 0; kk < Kdim; kk += 32){
        __syncthreads();
        {
            int row = tid >> 2;
            const float* ar = A + (size_t)(m0+row)*Kdim + kk;
            const float* wr = W + (size_t)(n0+row)*Kdim + kk;
            #pragma unroll
            for (int hh = 0; hh < 2; hh++){
                int kb = ((tid & 3) << 2) + (hh << 4);
                float4 va = *reinterpret_cast<const float4*>(ar + kb);
                As[kb+0][row] = make_float2(va.x, va.x);
                As[kb+1][row] = make_float2(va.y, va.y);
                As[kb+2][row] = make_float2(va.z, va.z);
                As[kb+3][row] = make_float2(va.w, va.w);
                float4 vw = *reinterpret_cast<const float4*>(wr + kb);
                Ws[kb+0][row] = vw.x; Ws[kb+1][row] = vw.y;
                Ws[kb+2][row] = vw.z; Ws[kb+3][row] = vw.w;
            }
        }
        __syncthreads();
        #pragma unroll 8
        for (int k = 0; k < 32; k++){
            uu b0 = *reinterpret_cast<const uu*>(&Ws[k][tx << 1]);
            uu b1 = *reinterpret_cast<const uu*>(&Ws[k][(tx << 1) + 32]);
            #pragma unroll
            for (int r = 0; r < 4; r++){
                uu a = *reinterpret_cast<const uu*>(&As[k][(ty << 2) + r]);
                acc[r][0] = ffma2(a, b0, acc[r][0]);
                acc[r][1] = ffma2(a, b1, acc[r][1]);
            }
        }
    }
    #pragma unroll
    for (int r = 0; r < 4; r++){
        int row = m0 + (ty << 2) + r;
        #pragma unroll
        for (int p = 0; p < 2; p++){
            int j = (tx << 1) + (p << 5);
            float c0, c1;
            unpack2(acc[r][p], c0, c1);
            c0 = fmaxf(c0 + bias[n0+j],   0.0f);
            c1 = fmaxf(c1 + bias[n0+j+1], 0.0f);
            *reinterpret_cast<float2*>(&C[(size_t)row*Ndim + n0 + j]) = make_float2(c0, c1);
        }
    }
}

__global__ void __launch_bounds__(256) qkernel(
    const float* __restrict__ z, const float* __restrict__ cent, float* __restrict__ q)
{
    int warp = threadIdx.x >> 5, lane = threadIdx.x & 31;
    int b = blockIdx.x*8 + warp;
    float zr[8];
    #pragma unroll
    for (int i = 0; i < 8; i++) zr[i] = z[(size_t)b*Hsz + lane + 32*i];
    float s = 0.0f;
    for (int k = 0; k < Ksz; k++){
        float d = 0.0f;
        #pragma unroll
        for (int i = 0; i < 8; i++){
            float t = zr[i] - cent[k*Hsz + lane + 32*i];
            d = fmaf(t, t, d);
        }
        #pragma unroll
        for (int off = 16; off; off >>= 1) d += __shfl_xor_sync(0xffffffffu, d, off);
        if (lane == k) s = 1.0f / (1.0f + d);
    }
    float tot = s;
    #pragma unroll
    for (int off = 16; off; off >>= 1) tot += __shfl_xor_sync(0xffffffffu, tot, off);
    if (lane < Ksz) q[(size_t)b*Ksz + lane] = s / tot;
}

__global__ void __launch_bounds__(256) combine_kernel(
    const float* __restrict__ h2, const float* __restrict__ q,
    const float* __restrict__ eW3, const float* __restrict__ eb3, float* __restrict__ out)
{
    int warp = threadIdx.x >> 5, lane = threadIdx.x & 31;
    int b = blockIdx.x*8 + warp;
    float acc[Ksz][2];
    #pragma unroll
    for (int k = 0; k < Ksz; k++){ acc[k][0] = 0.0f; acc[k][1] = 0.0f; }
    for (int f = lane; f < E2sz; f += 32){
        #pragma unroll
        for (int k = 0; k < Ksz; k++){
            float hv = h2[((size_t)k*Bsz + b)*E2sz + f];
            acc[k][0] = fmaf(hv, eW3[(size_t)(k*2+0)*E2sz + f], acc[k][0]);
            acc[k][1] = fmaf(hv, eW3[(size_t)(k*2+1)*E2sz + f], acc[k][1]);
        }
    }
    #pragma unroll
    for (int k = 0; k < Ksz; k++)
        #pragma unroll
        for (int c = 0; c < 2; c++)
            #pragma unroll
            for (int off = 16; off; off >>= 1)
                acc[k][c] += __shfl_xor_sync(0xffffffffu, acc[k][c], off);
    if (lane == 0){
        float p0 = 0.0f, p1 = 0.0f;
        #pragma unroll
        for (int k = 0; k < Ksz; k++){
            float qq = q[(size_t)b*Ksz + k];
            p0 = fmaf(qq, acc[k][0] + eb3[k*2+0], p0);
            p1 = fmaf(qq, acc[k][1] + eb3[k*2+1], p1);
        }
        out[b*2+0] = p0; out[b*2+1] = p1;
    }
}

// ---------------------------------------------------------------------------
#define MMA_SMEM_FUSE  ((192 + 32) * 1024)
#define MMA_SMEM_PLAIN ((96 + 32) * 1024)
#define GI0_SMEM       (104 * 1024)

extern "C" void kernel_launch(void* const* d_in, const int* in_sizes, int n_in,
                              void* d_out, int out_size)
{
    const float* x    = (const float*)d_in[0];
    const float* Wih0 = (const float*)d_in[1];
    const float* Whh0 = (const float*)d_in[2];
    const float* bih0 = (const float*)d_in[3];
    const float* bhh0 = (const float*)d_in[4];
    const float* Wih1 = (const float*)d_in[5];
    const float* Whh1 = (const float*)d_in[6];
    const float* bih1 = (const float*)d_in[7];
    const float* bhh1 = (const float*)d_in[8];
    const float* cent = (const float*)d_in[9];
    const float* eW1  = (const float*)d_in[10];
    const float* eb1  = (const float*)d_in[11];
    const float* eW2  = (const float*)d_in[12];
    const float* eb2  = (const float*)d_in[13];
    const float* eW3  = (const float*)d_in[14];
    const float* eb3  = (const float*)d_in[15];
    float* out = (float*)d_out;

    float *gi0, *gi1, *z, *qb, *e1, *e2;
    __nv_bfloat16 *xB, *wihB0, *whhB0, *wihB1, *whhB1, *hB0, *hB1;
    unsigned *cnt0, *gen0, *cnt1, *gen1;
    cudaGetSymbolAddress((void**)&gi0,   g_gi0);
    cudaGetSymbolAddress((void**)&gi1,   g_gi1);
    cudaGetSymbolAddress((void**)&xB,    g_xB);
    cudaGetSymbolAddress((void**)&wihB0, g_WihB0);
    cudaGetSymbolAddress((void**)&whhB0, g_WhhB0);
    cudaGetSymbolAddress((void**)&wihB1, g_WihB1);
    cudaGetSymbolAddress((void**)&whhB1, g_WhhB1);
    cudaGetSymbolAddress((void**)&hB0,   g_hB0);
    cudaGetSymbolAddress((void**)&hB1,   g_hB1);
    cudaGetSymbolAddress((void**)&z,     g_z);
    cudaGetSymbolAddress((void**)&qb,    g_q);
    cudaGetSymbolAddress((void**)&e1,    g_e1);
    cudaGetSymbolAddress((void**)&e2,    g_e2);
    cudaGetSymbolAddress((void**)&cnt0,  g_cnt0);
    cudaGetSymbolAddress((void**)&gen0,  g_gen0);
    cudaGetSymbolAddress((void**)&cnt1,  g_cnt1);
    cudaGetSymbolAddress((void**)&gen1,  g_gen1);

    cudaFuncSetAttribute(gru_mma<true>,
                         cudaFuncAttributeMaxDynamicSharedMemorySize, MMA_SMEM_FUSE);
    cudaFuncSetAttribute(gru_mma<false>,
                         cudaFuncAttributeMaxDynamicSharedMemorySize, MMA_SMEM_PLAIN);
    cudaFuncSetAttribute(gi0_mma,
                         cudaFuncAttributeMaxDynamicSharedMemorySize, GI0_SMEM);

    const size_t WN  = (size_t)G3 * Hsz;
    const size_t WN0 = (size_t)G3 * Isz;
    const size_t XN  = (size_t)MT * Isz;

    // ---- bf16 hi/lo splits ----
    cvt_split<<<(int)(XN/256), 256>>>(x, xB, xB + XN, (int)XN);
    cvt_split<<<(int)((WN0+255)/256), 256>>>(Wih0, wihB0, wihB0 + WN0, (int)WN0);
    cvt_split<<<(int)(WN/256), 256>>>(Whh0, whhB0, whhB0 + WN, (int)WN);
    cvt_split<<<(int)(WN/256), 256>>>(Wih1, wihB1, wihB1 + WN, (int)WN);
    cvt_split<<<(int)(WN/256), 256>>>(Whh1, whhB1, whhB1 + WN, (int)WN);

    // ---- gi0 = x @ Wih0^T (tensor) ----
    gi0_mma<<<dim3(8, MT/64), 256, GI0_SMEM>>>(xB, xB + XN, wihB0, wihB0 + WN0, gi0);

    // ---- persistent tensor chains ----
    gru_mma<true><<<dim3(16, 8), 256, MMA_SMEM_FUSE>>>(
        whhB0, whhB0 + WN, wihB1, wihB1 + WN, gi0, bih0, bhh0,
        hB0, gi1, nullptr, cnt0, gen0);
    gru_mma<false><<<dim3(16, 8), 256, MMA_SMEM_PLAIN>>>(
        whhB1, whhB1 + WN, nullptr, nullptr, gi1, bih1, bhh1,
        hB1, nullptr, z, cnt1, gen1);

    // ---- clustering + experts + combine ----
    qkernel<<<128, 256>>>(z, cent, qb);
    gemm_relu_kernel<<<dim3(16, 8, 8), 256>>>(
        z, (size_t)0, eW1, (size_t)E1sz*Hsz, eb1, (size_t)E1sz,
        e1, (size_t)Bsz*E1sz, Hsz, E1sz);
    gemm_relu_kernel<<<dim3(16, 4, 8), 256>>>(
        e1, (size_t)Bsz*E1sz, eW2, (size_t)E2sz*E1sz, eb2, (size_t)E2sz,
        e2, (size_t)Bsz*E2sz, E1sz, E2sz);
    combine_kernel<<<128, 256>>>(e2, qb, eW3, eb3, out);

    (void)in_sizes; (void)n_in; (void)out_size;
}

// round 11
// speedup vs baseline: 2.0997x; 1.0405x over previous
#include <cuda_runtime.h>
#include <cuda_bf16.h>
#include <cstddef>

#define Bsz  1024
#define Tsz  128
#define Isz  128
#define Hsz  256
#define G3   768
#define Ksz  8
#define E1sz 512
#define E2sz 256
#define MT   (Bsz * Tsz)

typedef unsigned long long u64;
typedef unsigned int u32;

__device__ __forceinline__ float sigmoidf_(float x){ return __fdividef(1.0f, 1.0f + __expf(-x)); }
__device__ __forceinline__ float tanhf_(float x){ return 1.0f - __fdividef(2.0f, __expf(2.0f*x) + 1.0f); }

__device__ __forceinline__ u32 smem_u32(const void* p){
    u32 a; asm("{ .reg .u64 t; cvta.to.shared.u64 t, %1; cvt.u32.u64 %0, t; }" : "=r"(a) : "l"(p)); return a;
}
__device__ __forceinline__ void ldmA(u32 a, u32& r0, u32& r1, u32& r2, u32& r3){
    asm volatile("ldmatrix.sync.aligned.m8n8.x4.shared.b16 {%0,%1,%2,%3},[%4];"
                 : "=r"(r0),"=r"(r1),"=r"(r2),"=r"(r3) : "r"(a));
}
__device__ __forceinline__ void ldmB(u32 a, u32& r0, u32& r1){
    asm volatile("ldmatrix.sync.aligned.m8n8.x2.shared.b16 {%0,%1},[%2];"
                 : "=r"(r0),"=r"(r1) : "r"(a));
}
__device__ __forceinline__ void mma16816(float* d, u32 a0,u32 a1,u32 a2,u32 a3,u32 b0,u32 b1){
    asm volatile("mma.sync.aligned.m16n8k16.row.col.f32.bf16.bf16.f32 "
                 "{%0,%1,%2,%3},{%4,%5,%6,%7},{%8,%9},{%0,%1,%2,%3};"
                 : "+f"(d[0]),"+f"(d[1]),"+f"(d[2]),"+f"(d[3])
                 : "r"(a0),"r"(a1),"r"(a2),"r"(a3),"r"(b0),"r"(b1));
}

#define SWZ(row, c) ((u32)((((c) ^ ((row) & 7)) << 4)))

// ---------------- scratch ----------------
__device__ float g_gi0[(size_t)Tsz * Bsz * G3];
__device__ float g_gi1[(size_t)Tsz * Bsz * G3];
__device__ __nv_bfloat16 g_xB[2][(size_t)MT * Isz];
__device__ __nv_bfloat16 g_WihB0[2][(size_t)G3 * Isz];
__device__ __nv_bfloat16 g_WhhB0[2][(size_t)G3 * Hsz];
__device__ __nv_bfloat16 g_WihB1[2][(size_t)G3 * Hsz];
__device__ __nv_bfloat16 g_WhhB1[2][(size_t)G3 * Hsz];
__device__ __nv_bfloat16 g_hB0[4][(size_t)Bsz * Hsz];    // [hi_p0,hi_p1,lo_p0,lo_p1]
__device__ __nv_bfloat16 g_hB1[4][(size_t)Bsz * Hsz];
__device__ __nv_bfloat16 g_eW1B[2][(size_t)Ksz * E1sz * Hsz];
__device__ __nv_bfloat16 g_eW2B[2][(size_t)Ksz * E2sz * E1sz];
__device__ __nv_bfloat16 g_e1B[2][(size_t)Ksz * Bsz * E1sz];
__device__ float g_z[(size_t)Bsz * Hsz];
__device__ float g_q[Bsz * Ksz];
__device__ float g_e2[(size_t)Ksz * Bsz * E2sz];
// per-mx-group barriers (16 groups x 8-word padding)
__device__ unsigned g_cnt0[128], g_gen0[128], g_cnt1[128], g_gen1[128];

__device__ __forceinline__ void grid_bar(unsigned* cnt, volatile unsigned* gen,
                                         unsigned target, unsigned nCTAm1){
    __syncthreads();
    if (threadIdx.x == 0){
        __threadfence();
        if (atomicAdd(cnt, 1u) == nCTAm1){
            atomicExch(cnt, 0u); __threadfence(); *gen = target;
        } else { while (*gen < target) { } }
        __threadfence();
    }
    __syncthreads();
}

__global__ void __launch_bounds__(256) cvt_split(
    const float* __restrict__ in, __nv_bfloat16* __restrict__ hi,
    __nv_bfloat16* __restrict__ lo, int n)
{
    int i = blockIdx.x * 256 + threadIdx.x;
    if (i < n){
        float v = in[i];
        __nv_bfloat16 h = __float2bfloat16(v);
        hi[i] = h;
        lo[i] = __float2bfloat16(v - __bfloat162float(h));
    }
}

// ---------------------------------------------------------------------------
// mma_multi: load A frags once per k-chunk, feed up to 4 B operands.
// F = warp column groups of 8 (3 for gate tiles, 2 for expert tiles).
// ---------------------------------------------------------------------------
template<int NOPS, int KK, int RS, int F>
__device__ __forceinline__ void mma_multi(
    char* Asm,
    char* B0, float (&o0)[2][F][4], char* B1, float (&o1)[2][F][4],
    char* B2, float (&o2)[2][F][4], char* B3, float (&o3)[2][F][4],
    int lane, int wM, int wN)
{
    u32 aB = smem_u32(Asm);
    u32 bA0 = smem_u32(B0);
    u32 bA1 = (NOPS > 1) ? smem_u32(B1) : 0;
    u32 bA2 = (NOPS > 2) ? smem_u32(B2) : 0;
    u32 bA3 = (NOPS > 3) ? smem_u32(B3) : 0;
    const int ar0 = wM*32 + (lane & 15), ar1 = ar0 + 16;
    const int ah = lane >> 4;
    const int br = wN*(8*F) + (lane & 7);
    const int bh = (lane >> 3) & 1;
    #pragma unroll
    for (int kk = 0; kk < KK; kk++){
        int ac = kk*2 + ah, bc = kk*2 + bh;
        u32 x0,x1,x2,x3, y0,y1,y2,y3;
        ldmA(aB + (u32)(ar0*RS) + SWZ(ar0, ac), x0,x1,x2,x3);
        ldmA(aB + (u32)(ar1*RS) + SWZ(ar1, ac), y0,y1,y2,y3);
        #pragma unroll
        for (int f = 0; f < F; f++){
            int brr = br + f*8;
            u32 b0,b1;
            ldmB(bA0 + (u32)(brr*RS) + SWZ(brr, bc), b0,b1);
            mma16816(o0[0][f], x0,x1,x2,x3, b0,b1);
            mma16816(o0[1][f], y0,y1,y2,y3, b0,b1);
            if (NOPS > 1){
                ldmB(bA1 + (u32)(brr*RS) + SWZ(brr, bc), b0,b1);
                mma16816(o1[0][f], x0,x1,x2,x3, b0,b1);
                mma16816(o1[1][f], y0,y1,y2,y3, b0,b1);
            }
            if (NOPS > 2){
                ldmB(bA2 + (u32)(brr*RS) + SWZ(brr, bc), b0,b1);
                mma16816(o2[0][f], x0,x1,x2,x3, b0,b1);
                mma16816(o2[1][f], y0,y1,y2,y3, b0,b1);
            }
            if (NOPS > 3){
                ldmB(bA3 + (u32)(brr*RS) + SWZ(brr, bc), b0,b1);
                mma16816(o3[0][f], x0,x1,x2,x3, b0,b1);
                mma16816(o3[1][f], y0,y1,y2,y3, b0,b1);
            }
        }
    }
}

__device__ __forceinline__ void fill_A(char* Asm, const __nv_bfloat16* src, int m0, int tid){
    #pragma unroll
    for (int i = 0; i < 8; i++){
        int id = tid + i*256, row = id >> 5, c = id & 31;
        uint4 v = __ldcg(reinterpret_cast<const uint4*>(src + (size_t)(m0+row)*Hsz) + c);
        *reinterpret_cast<uint4*>(Asm + (size_t)row*512 + SWZ(row, c)) = v;
    }
}
__device__ __forceinline__ void pf_A(uint4 pf[8], const __nv_bfloat16* src, int m0, int tid){
    #pragma unroll
    for (int i = 0; i < 8; i++){
        int id = tid + i*256, row = id >> 5, c = id & 31;
        pf[i] = __ldcg(reinterpret_cast<const uint4*>(src + (size_t)(m0+row)*Hsz) + c);
    }
}
__device__ __forceinline__ void st_A(char* Asm, const uint4 pf[8], int tid){
    #pragma unroll
    for (int i = 0; i < 8; i++){
        int id = tid + i*256, row = id >> 5, c = id & 31;
        *reinterpret_cast<uint4*>(Asm + (size_t)row*512 + SWZ(row, c)) = pf[i];
    }
}
__device__ __forceinline__ void fill_B(char* dst, const __nv_bfloat16* W, int n0, int tid){
    for (int i = tid; i < 96*32; i += 256){
        int j = i >> 5, c = i & 31;
        int wrow = (j % 3)*Hsz + n0 + (j/3);
        uint4 v = *(reinterpret_cast<const uint4*>(W + (size_t)wrow*Hsz) + c);
        *reinterpret_cast<uint4*>(dst + (size_t)j*512 + SWZ(j, c)) = v;
    }
}
template<int F>
__device__ __forceinline__ void zero_acc(float (&a)[2][F][4]){
    #pragma unroll
    for (int m = 0; m < 2; m++)
        #pragma unroll
        for (int f = 0; f < F; f++)
            #pragma unroll
            for (int q = 0; q < 4; q++) a[m][f][q] = 0.0f;
}
__device__ __forceinline__ void store_gh(float* ghsm, float acc[2][3][4], int lane, int wM, int wN){
    #pragma unroll
    for (int m = 0; m < 2; m++)
        #pragma unroll
        for (int f = 0; f < 3; f++){
            int r0 = wM*32 + m*16 + (lane >> 2);
            int c0 = wN*24 + f*8 + 2*(lane & 3);
            *reinterpret_cast<float2*>(ghsm + r0*96 + c0)     = make_float2(acc[m][f][0], acc[m][f][1]);
            *reinterpret_cast<float2*>(ghsm + (r0+8)*96 + c0) = make_float2(acc[m][f][2], acc[m][f][3]);
        }
}
__device__ __forceinline__ void store_nat(float* ghsm, float acc[2][3][4], int lane, int wM, int wN){
    #pragma unroll
    for (int m = 0; m < 2; m++)
        #pragma unroll
        for (int f = 0; f < 3; f++){
            int r0 = wM*32 + m*16 + (lane >> 2);
            int j0 = wN*24 + f*8 + 2*(lane & 3);
            int n0c = (j0 % 3)*32 + j0/3;
            int n1c = ((j0+1) % 3)*32 + (j0+1)/3;
            ghsm[r0*96 + n0c]     = acc[m][f][0];
            ghsm[r0*96 + n1c]     = acc[m][f][1];
            ghsm[(r0+8)*96 + n0c] = acc[m][f][2];
            ghsm[(r0+8)*96 + n1c] = acc[m][f][3];
        }
}

// ---------------------------------------------------------------------------
// gi0 = x @ Wih0^T via bf16 MMA 3-pass (proven R10)
// ---------------------------------------------------------------------------
__global__ void __launch_bounds__(256) gi0_mma(
    const __nv_bfloat16* __restrict__ xHi, const __nv_bfloat16* __restrict__ xLo,
    const __nv_bfloat16* __restrict__ wHi, const __nv_bfloat16* __restrict__ wLo,
    float* __restrict__ gi0)
{
    extern __shared__ char smc[];
    char* Bhi = smc;
    char* Blo = smc + 24*1024;
    char* Ahi = smc + 48*1024;
    char* Alo = smc + 64*1024;
    float* ghsm = reinterpret_cast<float*>(smc + 48*1024);

    const int tid = threadIdx.x, lane = tid & 31, w = tid >> 5;
    const int wM = w >> 2, wN = w & 3;
    const int n0 = blockIdx.x * 32, m0 = blockIdx.y * 64;
    const size_t PG = (size_t)Bsz * G3;

    for (int i = tid; i < 96*16; i += 256){
        int j = i >> 4, c = i & 15;
        int wrow = (j % 3)*Hsz + n0 + (j/3);
        *reinterpret_cast<uint4*>(Bhi + (size_t)j*256 + SWZ(j, c)) =
            *(reinterpret_cast<const uint4*>(wHi + (size_t)wrow*Isz) + c);
        *reinterpret_cast<uint4*>(Blo + (size_t)j*256 + SWZ(j, c)) =
            *(reinterpret_cast<const uint4*>(wLo + (size_t)wrow*Isz) + c);
    }
    #pragma unroll
    for (int i = 0; i < 4; i++){
        int id = tid + i*256, row = id >> 4, c = id & 15;
        *reinterpret_cast<uint4*>(Ahi + (size_t)row*256 + SWZ(row, c)) =
            *(reinterpret_cast<const uint4*>(xHi + (size_t)(m0+row)*Isz) + c);
        *reinterpret_cast<uint4*>(Alo + (size_t)row*256 + SWZ(row, c)) =
            *(reinterpret_cast<const uint4*>(xLo + (size_t)(m0+row)*Isz) + c);
    }
    __syncthreads();

    float acc[2][3][4];
    zero_acc(acc);
    mma_multi<2, 8, 256, 3>(Ahi, Bhi, acc, Blo, acc, Bhi, acc, Bhi, acc, lane, wM, wN);
    mma_multi<1, 8, 256, 3>(Alo, Bhi, acc, Bhi, acc, Bhi, acc, Bhi, acc, lane, wM, wN);
    __syncthreads();
    store_nat(ghsm, acc, lane, wM, wN);
    __syncthreads();

    const int b = m0 >> 7, t0 = m0 & 127;
    #pragma unroll
    for (int i = 0; i < 6; i++){
        int fid = tid + i*256;
        int row = fid / 24, cq = fid % 24;
        int g = cq >> 3, hc4 = (cq & 7)*4;
        float4 v = *reinterpret_cast<const float4*>(ghsm + row*96 + g*32 + hc4);
        *reinterpret_cast<float4*>(gi0 + (size_t)(t0+row)*PG + (size_t)b*G3 + g*256 + n0 + hc4) = v;
    }
}

// ---------------------------------------------------------------------------
// Persistent tensor-core GRU layer (R10 skeleton + per-mx-group barriers)
// ---------------------------------------------------------------------------
template<bool FUSE>
__global__ void __launch_bounds__(256) gru_mma(
    const __nv_bfloat16* __restrict__ WhhHi, const __nv_bfloat16* __restrict__ WhhLo,
    const __nv_bfloat16* __restrict__ WihHi, const __nv_bfloat16* __restrict__ WihLo,
    const float* __restrict__ giAll, const float* __restrict__ bih,
    const float* __restrict__ bhh, __nv_bfloat16* __restrict__ hB,
    float* __restrict__ gi1out, float* __restrict__ zout,
    unsigned* cntArr, unsigned* genArr)
{
    extern __shared__ char smc[];
    char* B_hh_hi = smc;
    char* B_hh_lo = smc + 48*1024;
    char* B_ih_hi = smc + 96*1024;
    char* B_ih_lo = smc + 144*1024;
    char* Asm     = smc + (FUSE ? 192 : 96)*1024;
    float* ghsm   = reinterpret_cast<float*>(Asm);

    const int tid = threadIdx.x, lane = tid & 31, w = tid >> 5;
    const int wM = w >> 2, wN = w & 3;
    const int m0 = blockIdx.x * 64, n0 = blockIdx.y * 32;
    const size_t PG = (size_t)Bsz * G3, PHB = (size_t)Bsz * Hsz;
    unsigned* cnt = cntArr + blockIdx.x * 8;           // per-mx group (8 CTAs)
    volatile unsigned* gen = genArr + blockIdx.x * 8;

    fill_B(B_hh_hi, WhhHi, n0, tid);
    fill_B(B_hh_lo, WhhLo, n0, tid);
    if constexpr (FUSE){
        fill_B(B_ih_hi, WihHi, n0, tid);
        fill_B(B_ih_lo, WihLo, n0, tid);
    }

    const int hcol = tid & 31, rb = (tid >> 5) * 8;
    float br_ = bih[0*Hsz + n0 + hcol], bz_ = bih[1*Hsz + n0 + hcol], bn_ = bih[2*Hsz + n0 + hcol];
    float cr_ = bhh[0*Hsz + n0 + hcol], cz_ = bhh[1*Hsz + n0 + hcol], cn_ = bhh[2*Hsz + n0 + hcol];
    float h_own[8];
    #pragma unroll
    for (int i = 0; i < 8; i++) h_own[i] = 0.0f;

    const unsigned gbase = *gen;
    __syncthreads();

    for (int t = 0; t < Tsz; t++){
        float accG[2][3][4], accI[2][3][4];
        zero_acc(accG);
        if constexpr (FUSE) zero_acc(accI);

        if (t > 0){
            int pp = (t - 1) & 1;
            uint4 pf[8];
            pf_A(pf, hB + (size_t)(2 + pp) * PHB, m0, tid);
            fill_A(Asm, hB + (size_t)pp * PHB, m0, tid);
            __syncthreads();
            if constexpr (FUSE)
                mma_multi<4,16,512,3>(Asm, B_hh_hi, accG, B_hh_lo, accG,
                                      B_ih_hi, accI, B_ih_lo, accI, lane, wM, wN);
            else
                mma_multi<2,16,512,3>(Asm, B_hh_hi, accG, B_hh_lo, accG,
                                      B_hh_hi, accG, B_hh_hi, accG, lane, wM, wN);
            __syncthreads();
            st_A(Asm, pf, tid);
            __syncthreads();
            if constexpr (FUSE)
                mma_multi<2,16,512,3>(Asm, B_hh_hi, accG, B_ih_hi, accI,
                                      B_hh_hi, accG, B_hh_hi, accG, lane, wM, wN);
            else
                mma_multi<1,16,512,3>(Asm, B_hh_hi, accG, B_hh_hi, accG,
                                      B_hh_hi, accG, B_hh_hi, accG, lane, wM, wN);
            __syncthreads();
            store_gh(ghsm, accG, lane, wM, wN);
            __syncthreads();
        }

        // ---- epilogue ----
        {
            int pp = t & 1;
            __nv_bfloat16* hHiW = hB + (size_t)pp * PHB;
            __nv_bfloat16* hLoW = hB + (size_t)(2 + pp) * PHB;
            #pragma unroll
            for (int rr = 0; rr < 8; rr++){
                int row = rb + rr;
                float ghr = 0.0f, ghz = 0.0f, ghn = 0.0f;
                if (t > 0){
                    ghr = ghsm[row*96 + hcol*3 + 0];
                    ghz = ghsm[row*96 + hcol*3 + 1];
                    ghn = ghsm[row*96 + hcol*3 + 2];
                }
                const float* gp = giAll + (size_t)t*PG + (size_t)(m0+row)*G3 + n0 + hcol;
                float rg = sigmoidf_(gp[0]   + br_ + ghr + cr_);
                float zg = sigmoidf_(gp[256] + bz_ + ghz + cz_);
                float ng = tanhf_(gp[512] + bn_ + rg*(ghn + cn_));
                float hv = (1.0f - zg)*ng + zg*h_own[rr];
                h_own[rr] = hv;
                __nv_bfloat16 hh = __float2bfloat16(hv);
                size_t gidx = (size_t)(m0+row)*Hsz + n0 + hcol;
                hHiW[gidx] = hh;
                hLoW[gidx] = __float2bfloat16(hv - __bfloat162float(hh));
                if (!FUSE && t == Tsz-1) zout[gidx] = hv;
            }
        }

        if constexpr (FUSE){
            if (t > 0){
                __syncthreads();
                store_nat(ghsm, accI, lane, wM, wN);
                __syncthreads();
                float* go = gi1out + (size_t)(t-1)*PG;
                #pragma unroll
                for (int i = 0; i < 6; i++){
                    int fid = tid + i*256;
                    int row = fid / 24, cq = fid % 24;
                    int g = cq >> 3, hc4 = (cq & 7)*4;
                    float4 v = *reinterpret_cast<const float4*>(ghsm + row*96 + g*32 + hc4);
                    *reinterpret_cast<float4*>(go + (size_t)(m0+row)*G3 + g*256 + n0 + hc4) = v;
                }
            }
        }

        grid_bar(cnt, gen, gbase + (unsigned)t + 1u, 7u);
    }

    // ---- FUSE tail: gi1[127] ----
    if constexpr (FUSE){
        float accI[2][3][4];
        zero_acc(accI);
        int pp = (Tsz - 1) & 1;
        uint4 pf[8];
        pf_A(pf, hB + (size_t)(2 + pp) * PHB, m0, tid);
        fill_A(Asm, hB + (size_t)pp * PHB, m0, tid);
        __syncthreads();
        mma_multi<2,16,512,3>(Asm, B_ih_hi, accI, B_ih_lo, accI,
                              B_ih_hi, accI, B_ih_hi, accI, lane, wM, wN);
        __syncthreads();
        st_A(Asm, pf, tid);
        __syncthreads();
        mma_multi<1,16,512,3>(Asm, B_ih_hi, accI, B_ih_hi, accI,
                              B_ih_hi, accI, B_ih_hi, accI, lane, wM, wN);
        __syncthreads();
        store_nat(ghsm, accI, lane, wM, wN);
        __syncthreads();
        float* go = gi1out + (size_t)(Tsz-1)*PG;
        #pragma unroll
        for (int i = 0; i < 6; i++){
            int fid = tid + i*256;
            int row = fid / 24, cq = fid % 24;
            int g = cq >> 3, hc4 = (cq & 7)*4;
            float4 v = *reinterpret_cast<const float4*>(ghsm + row*96 + g*32 + hc4);
            *reinterpret_cast<float4*>(go + (size_t)(m0+row)*G3 + g*256 + n0 + hc4) = v;
        }
    }
}

// ---------------------------------------------------------------------------
// Expert GEMM on tensor cores: C[e] = relu(A[e] @ W[e]^T + bias[e])
// bf16 3-pass; tile 64x64; 8 warps (2m x 4n, F=2). K chunked by 128.
// EMIT_SPLIT: write bf16 hi/lo (feeds next tensor layer); else write f32.
// ---------------------------------------------------------------------------
template<int KDIM, bool EMIT_SPLIT>
__global__ void __launch_bounds__(256) gemm_expert(
    const __nv_bfloat16* __restrict__ aHi, const __nv_bfloat16* __restrict__ aLo,
    size_t aExpStride,
    const __nv_bfloat16* __restrict__ wHi, const __nv_bfloat16* __restrict__ wLo,
    const float* __restrict__ bias, int N,
    float* __restrict__ outF, __nv_bfloat16* __restrict__ outHi,
    __nv_bfloat16* __restrict__ outLo)
{
    extern __shared__ char smc[];
    char* Ah = smc;
    char* Al = smc + 16*1024;
    char* Bh = smc + 32*1024;
    char* Bl = smc + 48*1024;

    const int tid = threadIdx.x, lane = tid & 31, w = tid >> 5;
    const int wM = w >> 2, wN = w & 3;
    const int e = blockIdx.z;
    const int n0 = blockIdx.x * 64, m0 = blockIdx.y * 64;
    const __nv_bfloat16* Ahp = aHi + (size_t)e * aExpStride;
    const __nv_bfloat16* Alp = aLo + (size_t)e * aExpStride;
    const __nv_bfloat16* Whp = wHi + (size_t)e * N * KDIM;
    const __nv_bfloat16* Wlp = wLo + (size_t)e * N * KDIM;

    float acc[2][2][4];
    zero_acc(acc);

    for (int kc = 0; kc < KDIM; kc += 128){
        if (kc) __syncthreads();
        #pragma unroll
        for (int i = 0; i < 4; i++){
            int id = tid + i*256, r = id >> 4, c = id & 15;
            *reinterpret_cast<uint4*>(Ah + (size_t)r*256 + SWZ(r, c)) =
                *(reinterpret_cast<const uint4*>(Ahp + (size_t)(m0+r)*KDIM + kc) + c);
            *reinterpret_cast<uint4*>(Al + (size_t)r*256 + SWZ(r, c)) =
                *(reinterpret_cast<const uint4*>(Alp + (size_t)(m0+r)*KDIM + kc) + c);
            *reinterpret_cast<uint4*>(Bh + (size_t)r*256 + SWZ(r, c)) =
                *(reinterpret_cast<const uint4*>(Whp + (size_t)(n0+r)*KDIM + kc) + c);
            *reinterpret_cast<uint4*>(Bl + (size_t)r*256 + SWZ(r, c)) =
                *(reinterpret_cast<const uint4*>(Wlp + (size_t)(n0+r)*KDIM + kc) + c);
        }
        __syncthreads();
        mma_multi<2, 8, 256, 2>(Ah, Bh, acc, Bl, acc, Bh, acc, Bh, acc, lane, wM, wN);
        mma_multi<1, 8, 256, 2>(Al, Bh, acc, Bh, acc, Bh, acc, Bh, acc, lane, wM, wN);
    }

    const size_t ob = (size_t)e * Bsz * N;
    #pragma unroll
    for (int m = 0; m < 2; m++)
        #pragma unroll
        for (int f = 0; f < 2; f++){
            int r0 = m0 + wM*32 + m*16 + (lane >> 2);
            int c0 = n0 + wN*16 + f*8 + 2*(lane & 3);
            float b0v = bias[e*N + c0], b1v = bias[e*N + c0 + 1];
            #pragma unroll
            for (int hrow = 0; hrow < 2; hrow++){
                int r = r0 + hrow*8;
                float v0 = fmaxf(acc[m][f][hrow*2+0] + b0v, 0.0f);
                float v1 = fmaxf(acc[m][f][hrow*2+1] + b1v, 0.0f);
                if constexpr (EMIT_SPLIT){
                    __nv_bfloat16 h0 = __float2bfloat16(v0), h1 = __float2bfloat16(v1);
                    outHi[ob + (size_t)r*N + c0]     = h0;
                    outHi[ob + (size_t)r*N + c0 + 1] = h1;
                    outLo[ob + (size_t)r*N + c0]     = __float2bfloat16(v0 - __bfloat162float(h0));
                    outLo[ob + (size_t)r*N + c0 + 1] = __float2bfloat16(v1 - __bfloat162float(h1));
                } else {
                    *reinterpret_cast<float2*>(outF + ob + (size_t)r*N + c0) = make_float2(v0, v1);
                }
            }
        }
}

// ---------------- q / combine (proven) ----------------
__global__ void __launch_bounds__(256) qkernel(
    const float* __restrict__ z, const float* __restrict__ cent, float* __restrict__ q)
{
    int warp = threadIdx.x >> 5, lane = threadIdx.x & 31;
    int b = blockIdx.x*8 + warp;
    float zr[8];
    #pragma unroll
    for (int i = 0; i < 8; i++) zr[i] = z[(size_t)b*Hsz + lane + 32*i];
    float s = 0.0f;
    for (int k = 0; k < Ksz; k++){
        float d = 0.0f;
        #pragma unroll
        for (int i = 0; i < 8; i++){
            float t = zr[i] - cent[k*Hsz + lane + 32*i];
            d = fmaf(t, t, d);
        }
        #pragma unroll
        for (int off = 16; off; off >>= 1) d += __shfl_xor_sync(0xffffffffu, d, off);
        if (lane == k) s = 1.0f / (1.0f + d);
    }
    float tot = s;
    #pragma unroll
    for (int off = 16; off; off >>= 1) tot += __shfl_xor_sync(0xffffffffu, tot, off);
    if (lane < Ksz) q[(size_t)b*Ksz + lane] = s / tot;
}

__global__ void __launch_bounds__(256) combine_kernel(
    const float* __restrict__ h2, const float* __restrict__ q,
    const float* __restrict__ eW3, const float* __restrict__ eb3, float* __restrict__ out)
{
    int warp = threadIdx.x >> 5, lane = threadIdx.x & 31;
    int b = blockIdx.x*8 + warp;
    float acc[Ksz][2];
    #pragma unroll
    for (int k = 0; k < Ksz; k++){ acc[k][0] = 0.0f; acc[k][1] = 0.0f; }
    for (int f = lane; f < E2sz; f += 32){
        #pragma unroll
        for (int k = 0; k < Ksz; k++){
            float hv = h2[((size_t)k*Bsz + b)*E2sz + f];
            acc[k][0] = fmaf(hv, eW3[(size_t)(k*2+0)*E2sz + f], acc[k][0]);
            acc[k][1] = fmaf(hv, eW3[(size_t)(k*2+1)*E2sz + f], acc[k][1]);
        }
    }
    #pragma unroll
    for (int k = 0; k < Ksz; k++)
        #pragma unroll
        for (int c = 0; c < 2; c++)
            #pragma unroll
            for (int off = 16; off; off >>= 1)
                acc[k][c] += __shfl_xor_sync(0xffffffffu, acc[k][c], off);
    if (lane == 0){
        float p0 = 0.0f, p1 = 0.0f;
        #pragma unroll
        for (int k = 0; k < Ksz; k++){
            float qq = q[(size_t)b*Ksz + k];
            p0 = fmaf(qq, acc[k][0] + eb3[k*2+0], p0);
            p1 = fmaf(qq, acc[k][1] + eb3[k*2+1], p1);
        }
        out[b*2+0] = p0; out[b*2+1] = p1;
    }
}

// ---------------------------------------------------------------------------
#define MMA_SMEM_FUSE  ((192 + 32) * 1024)
#define MMA_SMEM_PLAIN ((96 + 32) * 1024)
#define GI0_SMEM       (104 * 1024)
#define EXP_SMEM       (64 * 1024)

extern "C" void kernel_launch(void* const* d_in, const int* in_sizes, int n_in,
                              void* d_out, int out_size)
{
    const float* x    = (const float*)d_in[0];
    const float* Wih0 = (const float*)d_in[1];
    const float* Whh0 = (const float*)d_in[2];
    const float* bih0 = (const float*)d_in[3];
    const float* bhh0 = (const float*)d_in[4];
    const float* Wih1 = (const float*)d_in[5];
    const float* Whh1 = (const float*)d_in[6];
    const float* bih1 = (const float*)d_in[7];
    const float* bhh1 = (const float*)d_in[8];
    const float* cent = (const float*)d_in[9];
    const float* eW1  = (const float*)d_in[10];
    const float* eb1  = (const float*)d_in[11];
    const float* eW2  = (const float*)d_in[12];
    const float* eb2  = (const float*)d_in[13];
    const float* eW3  = (const float*)d_in[14];
    const float* eb3  = (const float*)d_in[15];
    float* out = (float*)d_out;

    float *gi0, *gi1, *z, *qb, *e2;
    __nv_bfloat16 *xB, *wihB0, *whhB0, *wihB1, *whhB1, *hB0, *hB1, *eW1B, *eW2B, *e1B;
    unsigned *cnt0, *gen0, *cnt1, *gen1;
    cudaGetSymbolAddress((void**)&gi0,   g_gi0);
    cudaGetSymbolAddress((void**)&gi1,   g_gi1);
    cudaGetSymbolAddress((void**)&xB,    g_xB);
    cudaGetSymbolAddress((void**)&wihB0, g_WihB0);
    cudaGetSymbolAddress((void**)&whhB0, g_WhhB0);
    cudaGetSymbolAddress((void**)&wihB1, g_WihB1);
    cudaGetSymbolAddress((void**)&whhB1, g_WhhB1);
    cudaGetSymbolAddress((void**)&hB0,   g_hB0);
    cudaGetSymbolAddress((void**)&hB1,   g_hB1);
    cudaGetSymbolAddress((void**)&eW1B,  g_eW1B);
    cudaGetSymbolAddress((void**)&eW2B,  g_eW2B);
    cudaGetSymbolAddress((void**)&e1B,   g_e1B);
    cudaGetSymbolAddress((void**)&z,     g_z);
    cudaGetSymbolAddress((void**)&qb,    g_q);
    cudaGetSymbolAddress((void**)&e2,    g_e2);
    cudaGetSymbolAddress((void**)&cnt0,  g_cnt0);
    cudaGetSymbolAddress((void**)&gen0,  g_gen0);
    cudaGetSymbolAddress((void**)&cnt1,  g_cnt1);
    cudaGetSymbolAddress((void**)&gen1,  g_gen1);

    cudaFuncSetAttribute(gru_mma<true>,
                         cudaFuncAttributeMaxDynamicSharedMemorySize, MMA_SMEM_FUSE);
    cudaFuncSetAttribute(gru_mma<false>,
                         cudaFuncAttributeMaxDynamicSharedMemorySize, MMA_SMEM_PLAIN);
    cudaFuncSetAttribute(gi0_mma,
                         cudaFuncAttributeMaxDynamicSharedMemorySize, GI0_SMEM);
    cudaFuncSetAttribute(gemm_expert<256, true>,
                         cudaFuncAttributeMaxDynamicSharedMemorySize, EXP_SMEM);
    cudaFuncSetAttribute(gemm_expert<512, false>,
                         cudaFuncAttributeMaxDynamicSharedMemorySize, EXP_SMEM);

    const size_t WN  = (size_t)G3 * Hsz;
    const size_t WN0 = (size_t)G3 * Isz;
    const size_t XN  = (size_t)MT * Isz;
    const size_t W1N = (size_t)Ksz * E1sz * Hsz;
    const size_t W2N = (size_t)Ksz * E2sz * E1sz;
    const size_t PHB = (size_t)Bsz * Hsz;

    // ---- bf16 hi/lo splits ----
    cvt_split<<<(int)(XN/256), 256>>>(x, xB, xB + XN, (int)XN);
    cvt_split<<<(int)((WN0+255)/256), 256>>>(Wih0, wihB0, wihB0 + WN0, (int)WN0);
    cvt_split<<<(int)(WN/256), 256>>>(Whh0, whhB0, whhB0 + WN, (int)WN);
    cvt_split<<<(int)(WN/256), 256>>>(Wih1, wihB1, wihB1 + WN, (int)WN);
    cvt_split<<<(int)(WN/256), 256>>>(Whh1, whhB1, whhB1 + WN, (int)WN);
    cvt_split<<<(int)(W1N/256), 256>>>(eW1, eW1B, eW1B + W1N, (int)W1N);
    cvt_split<<<(int)(W2N/256), 256>>>(eW2, eW2B, eW2B + W2N, (int)W2N);

    // ---- gi0 = x @ Wih0^T (tensor) ----
    gi0_mma<<<dim3(8, MT/64), 256, GI0_SMEM>>>(xB, xB + XN, wihB0, wihB0 + WN0, gi0);

    // ---- persistent tensor chains (per-mx-group barriers) ----
    gru_mma<true><<<dim3(16, 8), 256, MMA_SMEM_FUSE>>>(
        whhB0, whhB0 + WN, wihB1, wihB1 + WN, gi0, bih0, bhh0,
        hB0, gi1, nullptr, cnt0, gen0);
    gru_mma<false><<<dim3(16, 8), 256, MMA_SMEM_PLAIN>>>(
        whhB1, whhB1 + WN, nullptr, nullptr, gi1, bih1, bhh1,
        hB1, nullptr, z, cnt1, gen1);

    // ---- clustering + tensor experts + combine ----
    qkernel<<<128, 256>>>(z, cent, qb);
    // z hi/lo are hB1 planes 1 (hi) and 3 (lo) after 128 steps
    gemm_expert<256, true><<<dim3(8, 16, 8), 256, EXP_SMEM>>>(
        hB1 + PHB, hB1 + 3*PHB, (size_t)0, eW1B, eW1B + W1N, eb1, E1sz,
        nullptr, e1B, e1B + (size_t)Ksz*Bsz*E1sz);
    gemm_expert<512, false><<<dim3(4, 16, 8), 256, EXP_SMEM>>>(
        e1B, e1B + (size_t)Ksz*Bsz*E1sz, (size_t)Bsz*E1sz, eW2B, eW2B + W2N, eb2, E2sz,
        e2, nullptr, nullptr);
    combine_kernel<<<128, 256>>>(e2, qb, eW3, eb3, out);

    (void)in_sizes; (void)n_in; (void)out_size;
}

// round 14
// speedup vs baseline: 2.4563x; 1.1698x over previous
#include <cuda_runtime.h>
#include <cuda_bf16.h>
#include <cstddef>

#define Bsz  1024
#define Tsz  128
#define Isz  128
#define Hsz  256
#define G3   768
#define Ksz  8
#define E1sz 512
#define E2sz 256
#define MT   (Bsz * Tsz)

typedef unsigned long long u64;
typedef unsigned int u32;

__device__ __forceinline__ float sigmoidf_(float x){ return __fdividef(1.0f, 1.0f + __expf(-x)); }
__device__ __forceinline__ float tanhf_(float x){ return 1.0f - __fdividef(2.0f, __expf(2.0f*x) + 1.0f); }

__device__ __forceinline__ u32 smem_u32(const void* p){
    u32 a; asm("{ .reg .u64 t; cvta.to.shared.u64 t, %1; cvt.u32.u64 %0, t; }" : "=r"(a) : "l"(p)); return a;
}
__device__ __forceinline__ void ldmA(u32 a, u32& r0, u32& r1, u32& r2, u32& r3){
    asm volatile("ldmatrix.sync.aligned.m8n8.x4.shared.b16 {%0,%1,%2,%3},[%4];"
                 : "=r"(r0),"=r"(r1),"=r"(r2),"=r"(r3) : "r"(a));
}
__device__ __forceinline__ void ldmB(u32 a, u32& r0, u32& r1){
    asm volatile("ldmatrix.sync.aligned.m8n8.x2.shared.b16 {%0,%1},[%2];"
                 : "=r"(r0),"=r"(r1) : "r"(a));
}
__device__ __forceinline__ void mma16816(float* d, u32 a0,u32 a1,u32 a2,u32 a3,u32 b0,u32 b1){
    asm volatile("mma.sync.aligned.m16n8k16.row.col.f32.bf16.bf16.f32 "
                 "{%0,%1,%2,%3},{%4,%5,%6,%7},{%8,%9},{%0,%1,%2,%3};"
                 : "+f"(d[0]),"+f"(d[1]),"+f"(d[2]),"+f"(d[3])
                 : "r"(a0),"r"(a1),"r"(a2),"r"(a3),"r"(b0),"r"(b1));
}
#define SWZ(row, c) ((u32)((((c) ^ ((row) & 7)) << 4)))

// ---------------- scratch ----------------
__device__ float g_gi0[(size_t)Tsz * Bsz * G3];
__device__ float g_gi1[(size_t)Tsz * Bsz * G3];
__device__ __nv_bfloat16 g_xB[2][(size_t)MT * Isz];
__device__ __nv_bfloat16 g_WihB0[2][(size_t)G3 * Isz];
__device__ __nv_bfloat16 g_WhhB0[2][(size_t)G3 * Hsz];
__device__ __nv_bfloat16 g_WihB1[2][(size_t)G3 * Hsz];
__device__ __nv_bfloat16 g_WhhB1[2][(size_t)G3 * Hsz];
__device__ __nv_bfloat16 g_hB0[4][(size_t)Bsz * Hsz];    // [hi_p0,hi_p1,lo_p0,lo_p1]
__device__ __nv_bfloat16 g_hB1[4][(size_t)Bsz * Hsz];
__device__ __nv_bfloat16 g_eW1B[2][(size_t)Ksz * E1sz * Hsz];
__device__ __nv_bfloat16 g_eW2B[2][(size_t)Ksz * E2sz * E1sz];
__device__ __nv_bfloat16 g_e1B[2][(size_t)Ksz * Bsz * E1sz];
__device__ float g_z[(size_t)Bsz * Hsz];
__device__ float g_q[Bsz * Ksz];
__device__ float g_e2[(size_t)Ksz * Bsz * E2sz];
__device__ unsigned g_cnt0[128], g_gen0[128], g_cnt1[128], g_gen1[128];

__device__ __forceinline__ void grid_bar(unsigned* cnt, volatile unsigned* gen,
                                         unsigned target, unsigned nCTAm1){
    __syncthreads();
    if (threadIdx.x == 0){
        __threadfence();
        if (atomicAdd(cnt, 1u) == nCTAm1){
            atomicExch(cnt, 0u); __threadfence(); *gen = target;
        } else { while (*gen < target) { } }
        __threadfence();
    }
    __syncthreads();
}

__global__ void __launch_bounds__(256) cvt_split(
    const float* __restrict__ in, __nv_bfloat16* __restrict__ hi,
    __nv_bfloat16* __restrict__ lo, int n)
{
    int i = blockIdx.x * 256 + threadIdx.x;
    if (i < n){
        float v = in[i];
        __nv_bfloat16 h = __float2bfloat16(v);
        hi[i] = h;
        lo[i] = __float2bfloat16(v - __bfloat162float(h));
    }
}

// ---------------------------------------------------------------------------
// mma_multi (proven R11)
// ---------------------------------------------------------------------------
template<int NOPS, int KK, int RS, int F>
__device__ __forceinline__ void mma_multi(
    char* Asm,
    char* B0, float (&o0)[2][F][4], char* B1, float (&o1)[2][F][4],
    char* B2, float (&o2)[2][F][4], char* B3, float (&o3)[2][F][4],
    int lane, int wM, int wN)
{
    u32 aB = smem_u32(Asm);
    u32 bA0 = smem_u32(B0);
    u32 bA1 = (NOPS > 1) ? smem_u32(B1) : 0;
    u32 bA2 = (NOPS > 2) ? smem_u32(B2) : 0;
    u32 bA3 = (NOPS > 3) ? smem_u32(B3) : 0;
    const int ar0 = wM*32 + (lane & 15), ar1 = ar0 + 16;
    const int ah = lane >> 4;
    const int br = wN*(8*F) + (lane & 7);
    const int bh = (lane >> 3) & 1;
    #pragma unroll
    for (int kk = 0; kk < KK; kk++){
        int ac = kk*2 + ah, bc = kk*2 + bh;
        u32 x0,x1,x2,x3, y0,y1,y2,y3;
        ldmA(aB + (u32)(ar0*RS) + SWZ(ar0, ac), x0,x1,x2,x3);
        ldmA(aB + (u32)(ar1*RS) + SWZ(ar1, ac), y0,y1,y2,y3);
        #pragma unroll
        for (int f = 0; f < F; f++){
            int brr = br + f*8;
            u32 b0,b1;
            ldmB(bA0 + (u32)(brr*RS) + SWZ(brr, bc), b0,b1);
            mma16816(o0[0][f], x0,x1,x2,x3, b0,b1);
            mma16816(o0[1][f], y0,y1,y2,y3, b0,b1);
            if (NOPS > 1){
                ldmB(bA1 + (u32)(brr*RS) + SWZ(brr, bc), b0,b1);
                mma16816(o1[0][f], x0,x1,x2,x3, b0,b1);
                mma16816(o1[1][f], y0,y1,y2,y3, b0,b1);
            }
            if (NOPS > 2){
                ldmB(bA2 + (u32)(brr*RS) + SWZ(brr, bc), b0,b1);
                mma16816(o2[0][f], x0,x1,x2,x3, b0,b1);
                mma16816(o2[1][f], y0,y1,y2,y3, b0,b1);
            }
            if (NOPS > 3){
                ldmB(bA3 + (u32)(brr*RS) + SWZ(brr, bc), b0,b1);
                mma16816(o3[0][f], x0,x1,x2,x3, b0,b1);
                mma16816(o3[1][f], y0,y1,y2,y3, b0,b1);
            }
        }
    }
}

__device__ __forceinline__ void fill_A(char* Asm, const __nv_bfloat16* src, int m0, int tid){
    #pragma unroll
    for (int i = 0; i < 8; i++){
        int id = tid + i*256, row = id >> 5, c = id & 31;
        uint4 v = __ldcg(reinterpret_cast<const uint4*>(src + (size_t)(m0+row)*Hsz) + c);
        *reinterpret_cast<uint4*>(Asm + (size_t)row*512 + SWZ(row, c)) = v;
    }
}
__device__ __forceinline__ void pf_A(uint4 pf[8], const __nv_bfloat16* src, int m0, int tid){
    #pragma unroll
    for (int i = 0; i < 8; i++){
        int id = tid + i*256, row = id >> 5, c = id & 31;
        pf[i] = __ldcg(reinterpret_cast<const uint4*>(src + (size_t)(m0+row)*Hsz) + c);
    }
}
__device__ __forceinline__ void st_A(char* Asm, const uint4 pf[8], int tid){
    #pragma unroll
    for (int i = 0; i < 8; i++){
        int id = tid + i*256, row = id >> 5, c = id & 31;
        *reinterpret_cast<uint4*>(Asm + (size_t)row*512 + SWZ(row, c)) = pf[i];
    }
}
// chain B fill, gate-major within each warp's 24-col span:
// tile row j: group=j/24, gate=(j>>3)%3, k=j&7 -> W row = gate*Hsz + n0 + group*8 + k
__device__ __forceinline__ void fill_Bg(char* dst, const __nv_bfloat16* W, int n0, int tid){
    for (int i = tid; i < 96*32; i += 256){
        int j = i >> 5, c = i & 31;
        int wrow = ((j >> 3) % 3)*Hsz + n0 + (j/24)*8 + (j & 7);
        uint4 v = *(reinterpret_cast<const uint4*>(W + (size_t)wrow*Hsz) + c);
        *reinterpret_cast<uint4*>(dst + (size_t)j*512 + SWZ(j, c)) = v;
    }
}
template<int F>
__device__ __forceinline__ void zero_acc(float (&a)[2][F][4]){
    #pragma unroll
    for (int m = 0; m < 2; m++)
        #pragma unroll
        for (int f = 0; f < F; f++)
            #pragma unroll
            for (int q = 0; q < 4; q++) a[m][f][q] = 0.0f;
}
__device__ __forceinline__ void store_nat(float* ghsm, float acc[2][3][4], int lane, int wM, int wN){
    #pragma unroll
    for (int m = 0; m < 2; m++)
        #pragma unroll
        for (int f = 0; f < 3; f++){
            int r0 = wM*32 + m*16 + (lane >> 2);
            int j0 = wN*24 + f*8 + 2*(lane & 3);
            int n0c = (j0 % 3)*32 + j0/3;
            int n1c = ((j0+1) % 3)*32 + (j0+1)/3;
            ghsm[r0*96 + n0c]     = acc[m][f][0];
            ghsm[r0*96 + n1c]     = acc[m][f][1];
            ghsm[(r0+8)*96 + n0c] = acc[m][f][2];
            ghsm[(r0+8)*96 + n1c] = acc[m][f][3];
        }
}

// ---------------------------------------------------------------------------
// gi0 = x @ Wih0^T (proven R10/R11, unchanged: own fill + store_nat)
// ---------------------------------------------------------------------------
__global__ void __launch_bounds__(256) gi0_mma(
    const __nv_bfloat16* __restrict__ xHi, const __nv_bfloat16* __restrict__ xLo,
    const __nv_bfloat16* __restrict__ wHi, const __nv_bfloat16* __restrict__ wLo,
    float* __restrict__ gi0)
{
    extern __shared__ char smc[];
    char* Bhi = smc;
    char* Blo = smc + 24*1024;
    char* Ahi = smc + 48*1024;
    char* Alo = smc + 64*1024;
    float* ghsm = reinterpret_cast<float*>(smc + 48*1024);

    const int tid = threadIdx.x, lane = tid & 31, w = tid >> 5;
    const int wM = w >> 2, wN = w & 3;
    const int n0 = blockIdx.x * 32, m0 = blockIdx.y * 64;
    const size_t PG = (size_t)Bsz * G3;

    for (int i = tid; i < 96*16; i += 256){
        int j = i >> 4, c = i & 15;
        int wrow = (j % 3)*Hsz + n0 + (j/3);
        *reinterpret_cast<uint4*>(Bhi + (size_t)j*256 + SWZ(j, c)) =
            *(reinterpret_cast<const uint4*>(wHi + (size_t)wrow*Isz) + c);
        *reinterpret_cast<uint4*>(Blo + (size_t)j*256 + SWZ(j, c)) =
            *(reinterpret_cast<const uint4*>(wLo + (size_t)wrow*Isz) + c);
    }
    #pragma unroll
    for (int i = 0; i < 4; i++){
        int id = tid + i*256, row = id >> 4, c = id & 15;
        *reinterpret_cast<uint4*>(Ahi + (size_t)row*256 + SWZ(row, c)) =
            *(reinterpret_cast<const uint4*>(xHi + (size_t)(m0+row)*Isz) + c);
        *reinterpret_cast<uint4*>(Alo + (size_t)row*256 + SWZ(row, c)) =
            *(reinterpret_cast<const uint4*>(xLo + (size_t)(m0+row)*Isz) + c);
    }
    __syncthreads();

    float acc[2][3][4];
    zero_acc(acc);
    mma_multi<2, 8, 256, 3>(Ahi, Bhi, acc, Blo, acc, Bhi, acc, Bhi, acc, lane, wM, wN);
    mma_multi<1, 8, 256, 3>(Alo, Bhi, acc, Bhi, acc, Bhi, acc, Bhi, acc, lane, wM, wN);
    __syncthreads();
    store_nat(ghsm, acc, lane, wM, wN);
    __syncthreads();

    const int b = m0 >> 7, t0 = m0 & 127;
    #pragma unroll
    for (int i = 0; i < 6; i++){
        int fid = tid + i*256;
        int row = fid / 24, cq = fid % 24;
        int g = cq >> 3, hc4 = (cq & 7)*4;
        float4 v = *reinterpret_cast<const float4*>(ghsm + row*96 + g*32 + hc4);
        *reinterpret_cast<float4*>(gi0 + (size_t)(t0+row)*PG + (size_t)b*G3 + g*256 + n0 + hc4) = v;
    }
}

// ---------------------------------------------------------------------------
// Persistent HMMA GRU chain: gate-major B, register-local epilogue,
// gi prefetch, PLAIN dual-A single-sync.
// ---------------------------------------------------------------------------
template<bool FUSE>
__global__ void __launch_bounds__(256) gru_mma(
    const __nv_bfloat16* __restrict__ WhhHi, const __nv_bfloat16* __restrict__ WhhLo,
    const __nv_bfloat16* __restrict__ WihHi, const __nv_bfloat16* __restrict__ WihLo,
    const float* __restrict__ giAll, const float* __restrict__ bih,
    const float* __restrict__ bhh, __nv_bfloat16* __restrict__ hB,
    float* __restrict__ gi1out, float* __restrict__ zout,
    unsigned* cntArr, unsigned* genArr)
{
    extern __shared__ char smc[];
    __shared__ float sB[192];
    char* B_hh_hi = smc;
    char* B_hh_lo = smc + 48*1024;
    char* B_ih_hi = smc + 96*1024;     // FUSE only
    char* B_ih_lo = smc + 144*1024;    // FUSE only
    char* A1 = smc + (FUSE ? 192 : 96)*1024;
    char* A2 = FUSE ? A1 : (A1 + 32*1024);

    const int tid = threadIdx.x, lane = tid & 31, w = tid >> 5;
    const int wM = w >> 2, wN = w & 3;
    const int m0 = blockIdx.x * 64, n0 = blockIdx.y * 32;
    const size_t PG = (size_t)Bsz * G3, PHB = (size_t)Bsz * Hsz;
    unsigned* cnt = cntArr + blockIdx.x * 8;
    volatile unsigned* gen = genArr + blockIdx.x * 8;

    fill_Bg(B_hh_hi, WhhHi, n0, tid);
    fill_Bg(B_hh_lo, WhhLo, n0, tid);
    if constexpr (FUSE){
        fill_Bg(B_ih_hi, WihHi, n0, tid);
        fill_Bg(B_ih_lo, WihLo, n0, tid);
    }
    if (tid < 192){
        int g = tid >> 5, c = tid & 31;
        sB[tid] = (g < 3) ? bih[g*Hsz + n0 + c] : bhh[(g-3)*Hsz + n0 + c];
    }

    const int cl = wN*8 + 2*(lane & 3);       // local col base (0..30, even)
    const int colb = n0 + cl;                 // global h col base
    const int rloc = wM*32 + (lane >> 2);     // local row base
    float h_own[2][2][2];
    #pragma unroll
    for (int m = 0; m < 2; m++)
        #pragma unroll
        for (int hr = 0; hr < 2; hr++){ h_own[m][hr][0] = 0.0f; h_own[m][hr][1] = 0.0f; }

    const unsigned gbase = *gen;
    __syncthreads();

    for (int t = 0; t < Tsz; t++){
        float accG[2][3][4], accI[2][3][4];
        zero_acc(accG);
        if constexpr (FUSE) zero_acc(accI);
        float2 giv[2][2][3];

        if (t > 0){
            int pp = (t - 1) & 1;
            if constexpr (FUSE){
                uint4 pf[8];
                pf_A(pf, hB + (size_t)(2 + pp) * PHB, m0, tid);
                fill_A(A1, hB + (size_t)pp * PHB, m0, tid);
                __syncthreads();
                mma_multi<4,16,512,3>(A1, B_hh_hi, accG, B_hh_lo, accG,
                                      B_ih_hi, accI, B_ih_lo, accI, lane, wM, wN);
                __syncthreads();
                st_A(A1, pf, tid);
                __syncthreads();
                // gi prefetch (in flight during final pass)
                #pragma unroll
                for (int m = 0; m < 2; m++)
                    #pragma unroll
                    for (int hr = 0; hr < 2; hr++){
                        const float* gp = giAll + (size_t)t*PG
                            + (size_t)(m0 + rloc + m*16 + hr*8)*G3 + colb;
                        #pragma unroll
                        for (int g = 0; g < 3; g++)
                            giv[m][hr][g] = *reinterpret_cast<const float2*>(gp + g*256);
                    }
                mma_multi<2,16,512,3>(A1, B_hh_hi, accG, B_ih_hi, accI,
                                      B_hh_hi, accG, B_hh_hi, accG, lane, wM, wN);
            } else {
                // gi prefetch first (in flight through fills + mma)
                #pragma unroll
                for (int m = 0; m < 2; m++)
                    #pragma unroll
                    for (int hr = 0; hr < 2; hr++){
                        const float* gp = giAll + (size_t)t*PG
                            + (size_t)(m0 + rloc + m*16 + hr*8)*G3 + colb;
                        #pragma unroll
                        for (int g = 0; g < 3; g++)
                            giv[m][hr][g] = *reinterpret_cast<const float2*>(gp + g*256);
                    }
                fill_A(A1, hB + (size_t)pp * PHB, m0, tid);
                fill_A(A2, hB + (size_t)(2 + pp) * PHB, m0, tid);
                __syncthreads();
                mma_multi<2,16,512,3>(A1, B_hh_hi, accG, B_hh_lo, accG,
                                      B_hh_hi, accG, B_hh_hi, accG, lane, wM, wN);
                mma_multi<1,16,512,3>(A2, B_hh_hi, accG, B_hh_hi, accG,
                                      B_hh_hi, accG, B_hh_hi, accG, lane, wM, wN);
            }
        } else {
            #pragma unroll
            for (int m = 0; m < 2; m++)
                #pragma unroll
                for (int hr = 0; hr < 2; hr++){
                    const float* gp = giAll + (size_t)(m0 + rloc + m*16 + hr*8)*G3 + colb;
                    #pragma unroll
                    for (int g = 0; g < 3; g++)
                        giv[m][hr][g] = *reinterpret_cast<const float2*>(gp + g*256);
                }
        }

        // ---- register-local epilogue ----
        {
            int pp2 = t & 1;
            __nv_bfloat16* hHi = hB + (size_t)pp2 * PHB;
            __nv_bfloat16* hLo = hB + (size_t)(2 + pp2) * PHB;
            #pragma unroll
            for (int m = 0; m < 2; m++)
                #pragma unroll
                for (int hr = 0; hr < 2; hr++){
                    int row = m0 + rloc + m*16 + hr*8;
                    float hv2[2];
                    #pragma unroll
                    for (int cc = 0; cc < 2; cc++){
                        int q = hr*2 + cc;
                        float gr = (t > 0) ? accG[m][0][q] : 0.0f;
                        float gz = (t > 0) ? accG[m][1][q] : 0.0f;
                        float gn = (t > 0) ? accG[m][2][q] : 0.0f;
                        float gir = cc ? giv[m][hr][0].y : giv[m][hr][0].x;
                        float giz = cc ? giv[m][hr][1].y : giv[m][hr][1].x;
                        float gin = cc ? giv[m][hr][2].y : giv[m][hr][2].x;
                        float rg = sigmoidf_(gir + sB[cl+cc]      + gr + sB[96+cl+cc]);
                        float zg = sigmoidf_(giz + sB[32+cl+cc]   + gz + sB[128+cl+cc]);
                        float ng = tanhf_(gin + sB[64+cl+cc]      + rg*(gn + sB[160+cl+cc]));
                        float hv = (1.0f - zg)*ng + zg*h_own[m][hr][cc];
                        h_own[m][hr][cc] = hv;
                        hv2[cc] = hv;
                    }
                    __nv_bfloat162 hp, lp;
                    hp.x = __float2bfloat16(hv2[0]);
                    hp.y = __float2bfloat16(hv2[1]);
                    lp.x = __float2bfloat16(hv2[0] - __bfloat162float(hp.x));
                    lp.y = __float2bfloat16(hv2[1] - __bfloat162float(hp.y));
                    *reinterpret_cast<u32*>(hHi + (size_t)row*Hsz + colb) =
                        *reinterpret_cast<u32*>(&hp);
                    *reinterpret_cast<u32*>(hLo + (size_t)row*Hsz + colb) =
                        *reinterpret_cast<u32*>(&lp);
                    if (!FUSE && t == Tsz-1)
                        *reinterpret_cast<float2*>(zout + (size_t)row*Hsz + colb) =
                            make_float2(hv2[0], hv2[1]);
                    if (FUSE && t > 0){
                        float* go = gi1out + (size_t)(t-1)*PG + (size_t)row*G3;
                        #pragma unroll
                        for (int g = 0; g < 3; g++)
                            *reinterpret_cast<float2*>(go + g*256 + colb) =
                                make_float2(accI[m][g][hr*2], accI[m][g][hr*2+1]);
                    }
                }
        }

        grid_bar(cnt, gen, gbase + (unsigned)t + 1u, 7u);
    }

    // ---- FUSE tail: gi1[127] = h[127] @ Wih1^T ----
    if constexpr (FUSE){
        float accI[2][3][4];
        zero_acc(accI);
        int pp = (Tsz - 1) & 1;
        uint4 pf[8];
        pf_A(pf, hB + (size_t)(2 + pp) * PHB, m0, tid);
        fill_A(A1, hB + (size_t)pp * PHB, m0, tid);
        __syncthreads();
        mma_multi<2,16,512,3>(A1, B_ih_hi, accI, B_ih_lo, accI,
                              B_ih_hi, accI, B_ih_hi, accI, lane, wM, wN);
        __syncthreads();
        st_A(A1, pf, tid);
        __syncthreads();
        mma_multi<1,16,512,3>(A1, B_ih_hi, accI, B_ih_hi, accI,
                              B_ih_hi, accI, B_ih_hi, accI, lane, wM, wN);
        #pragma unroll
        for (int m = 0; m < 2; m++)
            #pragma unroll
            for (int hr = 0; hr < 2; hr++){
                int row = m0 + rloc + m*16 + hr*8;
                float* go = gi1out + (size_t)(Tsz-1)*PG + (size_t)row*G3;
                #pragma unroll
                for (int g = 0; g < 3; g++)
                    *reinterpret_cast<float2*>(go + g*256 + colb) =
                        make_float2(accI[m][g][hr*2], accI[m][g][hr*2+1]);
            }
    }
}

// ---------------------------------------------------------------------------
// Expert tensor GEMM (proven R11, unchanged)
// ---------------------------------------------------------------------------
template<int KDIM, bool EMIT_SPLIT>
__global__ void __launch_bounds__(256) gemm_expert(
    const __nv_bfloat16* __restrict__ aHi, const __nv_bfloat16* __restrict__ aLo,
    size_t aExpStride,
    const __nv_bfloat16* __restrict__ wHi, const __nv_bfloat16* __restrict__ wLo,
    const float* __restrict__ bias, int N,
    float* __restrict__ outF, __nv_bfloat16* __restrict__ outHi,
    __nv_bfloat16* __restrict__ outLo)
{
    extern __shared__ char smc[];
    char* Ah = smc;
    char* Al = smc + 16*1024;
    char* Bh = smc + 32*1024;
    char* Bl = smc + 48*1024;

    const int tid = threadIdx.x, lane = tid & 31, w = tid >> 5;
    const int wM = w >> 2, wN = w & 3;
    const int e = blockIdx.z;
    const int n0 = blockIdx.x * 64, m0 = blockIdx.y * 64;
    const __nv_bfloat16* Ahp = aHi + (size_t)e * aExpStride;
    const __nv_bfloat16* Alp = aLo + (size_t)e * aExpStride;
    const __nv_bfloat16* Whp = wHi + (size_t)e * N * KDIM;
    const __nv_bfloat16* Wlp = wLo + (size_t)e * N * KDIM;

    float acc[2][2][4];
    zero_acc(acc);

    for (int kc = 0; kc < KDIM; kc += 128){
        if (kc) __syncthreads();
        #pragma unroll
        for (int i = 0; i < 4; i++){
            int id = tid + i*256, r = id >> 4, c = id & 15;
            *reinterpret_cast<uint4*>(Ah + (size_t)r*256 + SWZ(r, c)) =
                *(reinterpret_cast<const uint4*>(Ahp + (size_t)(m0+r)*KDIM + kc) + c);
            *reinterpret_cast<uint4*>(Al + (size_t)r*256 + SWZ(r, c)) =
                *(reinterpret_cast<const uint4*>(Alp + (size_t)(m0+r)*KDIM + kc) + c);
            *reinterpret_cast<uint4*>(Bh + (size_t)r*256 + SWZ(r, c)) =
                *(reinterpret_cast<const uint4*>(Whp + (size_t)(n0+r)*KDIM + kc) + c);
            *reinterpret_cast<uint4*>(Bl + (size_t)r*256 + SWZ(r, c)) =
                *(reinterpret_cast<const uint4*>(Wlp + (size_t)(n0+r)*KDIM + kc) + c);
        }
        __syncthreads();
        mma_multi<2, 8, 256, 2>(Ah, Bh, acc, Bl, acc, Bh, acc, Bh, acc, lane, wM, wN);
        mma_multi<1, 8, 256, 2>(Al, Bh, acc, Bh, acc, Bh, acc, Bh, acc, lane, wM, wN);
    }

    const size_t ob = (size_t)e * Bsz * N;
    #pragma unroll
    for (int m = 0; m < 2; m++)
        #pragma unroll
        for (int f = 0; f < 2; f++){
            int r0 = m0 + wM*32 + m*16 + (lane >> 2);
            int c0 = n0 + wN*16 + f*8 + 2*(lane & 3);
            float b0v = bias[e*N + c0], b1v = bias[e*N + c0 + 1];
            #pragma unroll
            for (int hrow = 0; hrow < 2; hrow++){
                int r = r0 + hrow*8;
                float v0 = fmaxf(acc[m][f][hrow*2+0] + b0v, 0.0f);
                float v1 = fmaxf(acc[m][f][hrow*2+1] + b1v, 0.0f);
                if constexpr (EMIT_SPLIT){
                    __nv_bfloat16 h0 = __float2bfloat16(v0), h1 = __float2bfloat16(v1);
                    outHi[ob + (size_t)r*N + c0]     = h0;
                    outHi[ob + (size_t)r*N + c0 + 1] = h1;
                    outLo[ob + (size_t)r*N + c0]     = __float2bfloat16(v0 - __bfloat162float(h0));
                    outLo[ob + (size_t)r*N + c0 + 1] = __float2bfloat16(v1 - __bfloat162float(h1));
                } else {
                    *reinterpret_cast<float2*>(outF + ob + (size_t)r*N + c0) = make_float2(v0, v1);
                }
            }
        }
}

// ---------------- q / combine (proven) ----------------
__global__ void __launch_bounds__(256) qkernel(
    const float* __restrict__ z, const float* __restrict__ cent, float* __restrict__ q)
{
    int warp = threadIdx.x >> 5, lane = threadIdx.x & 31;
    int b = blockIdx.x*8 + warp;
    float zr[8];
    #pragma unroll
    for (int i = 0; i < 8; i++) zr[i] = z[(size_t)b*Hsz + lane + 32*i];
    float s = 0.0f;
    for (int k = 0; k < Ksz; k++){
        float d = 0.0f;
        #pragma unroll
        for (int i = 0; i < 8; i++){
            float t = zr[i] - cent[k*Hsz + lane + 32*i];
            d = fmaf(t, t, d);
        }
        #pragma unroll
        for (int off = 16; off; off >>= 1) d += __shfl_xor_sync(0xffffffffu, d, off);
        if (lane == k) s = 1.0f / (1.0f + d);
    }
    float tot = s;
    #pragma unroll
    for (int off = 16; off; off >>= 1) tot += __shfl_xor_sync(0xffffffffu, tot, off);
    if (lane < Ksz) q[(size_t)b*Ksz + lane] = s / tot;
}

__global__ void __launch_bounds__(256) combine_kernel(
    const float* __restrict__ h2, const float* __restrict__ q,
    const float* __restrict__ eW3, const float* __restrict__ eb3, float* __restrict__ out)
{
    int warp = threadIdx.x >> 5, lane = threadIdx.x & 31;
    int b = blockIdx.x*8 + warp;
    float acc[Ksz][2];
    #pragma unroll
    for (int k = 0; k < Ksz; k++){ acc[k][0] = 0.0f; acc[k][1] = 0.0f; }
    for (int f = lane; f < E2sz; f += 32){
        #pragma unroll
        for (int k = 0; k < Ksz; k++){
            float hv = h2[((size_t)k*Bsz + b)*E2sz + f];
            acc[k][0] = fmaf(hv, eW3[(size_t)(k*2+0)*E2sz + f], acc[k][0]);
            acc[k][1] = fmaf(hv, eW3[(size_t)(k*2+1)*E2sz + f], acc[k][1]);
        }
    }
    #pragma unroll
    for (int k = 0; k < Ksz; k++)
        #pragma unroll
        for (int c = 0; c < 2; c++)
            #pragma unroll
            for (int off = 16; off; off >>= 1)
                acc[k][c] += __shfl_xor_sync(0xffffffffu, acc[k][c], off);
    if (lane == 0){
        float p0 = 0.0f, p1 = 0.0f;
        #pragma unroll
        for (int k = 0; k < Ksz; k++){
            float qq = q[(size_t)b*Ksz + k];
            p0 = fmaf(qq, acc[k][0] + eb3[k*2+0], p0);
            p1 = fmaf(qq, acc[k][1] + eb3[k*2+1], p1);
        }
        out[b*2+0] = p0; out[b*2+1] = p1;
    }
}

// ---------------------------------------------------------------------------
#define MMA_SMEM_FUSE  ((192 + 32) * 1024)
#define MMA_SMEM_PLAIN ((96 + 64) * 1024)
#define GI0_SMEM       (104 * 1024)
#define EXP_SMEM       (64 * 1024)

extern "C" void kernel_launch(void* const* d_in, const int* in_sizes, int n_in,
                              void* d_out, int out_size)
{
    const float* x    = (const float*)d_in[0];
    const float* Wih0 = (const float*)d_in[1];
    const float* Whh0 = (const float*)d_in[2];
    const float* bih0 = (const float*)d_in[3];
    const float* bhh0 = (const float*)d_in[4];
    const float* Wih1 = (const float*)d_in[5];
    const float* Whh1 = (const float*)d_in[6];
    const float* bih1 = (const float*)d_in[7];
    const float* bhh1 = (const float*)d_in[8];
    const float* cent = (const float*)d_in[9];
    const float* eW1  = (const float*)d_in[10];
    const float* eb1  = (const float*)d_in[11];
    const float* eW2  = (const float*)d_in[12];
    const float* eb2  = (const float*)d_in[13];
    const float* eW3  = (const float*)d_in[14];
    const float* eb3  = (const float*)d_in[15];
    float* out = (float*)d_out;

    float *gi0, *gi1, *z, *qb, *e2;
    __nv_bfloat16 *xB, *wihB0, *whhB0, *wihB1, *whhB1, *hB0, *hB1, *eW1B, *eW2B, *e1B;
    unsigned *cnt0, *gen0, *cnt1, *gen1;
    cudaGetSymbolAddress((void**)&gi0,   g_gi0);
    cudaGetSymbolAddress((void**)&gi1,   g_gi1);
    cudaGetSymbolAddress((void**)&xB,    g_xB);
    cudaGetSymbolAddress((void**)&wihB0, g_WihB0);
    cudaGetSymbolAddress((void**)&whhB0, g_WhhB0);
    cudaGetSymbolAddress((void**)&wihB1, g_WihB1);
    cudaGetSymbolAddress((void**)&whhB1, g_WhhB1);
    cudaGetSymbolAddress((void**)&hB0,   g_hB0);
    cudaGetSymbolAddress((void**)&hB1,   g_hB1);
    cudaGetSymbolAddress((void**)&eW1B,  g_eW1B);
    cudaGetSymbolAddress((void**)&eW2B,  g_eW2B);
    cudaGetSymbolAddress((void**)&e1B,   g_e1B);
    cudaGetSymbolAddress((void**)&z,     g_z);
    cudaGetSymbolAddress((void**)&qb,    g_q);
    cudaGetSymbolAddress((void**)&e2,    g_e2);
    cudaGetSymbolAddress((void**)&cnt0,  g_cnt0);
    cudaGetSymbolAddress((void**)&gen0,  g_gen0);
    cudaGetSymbolAddress((void**)&cnt1,  g_cnt1);
    cudaGetSymbolAddress((void**)&gen1,  g_gen1);

    cudaFuncSetAttribute(gru_mma<true>,
                         cudaFuncAttributeMaxDynamicSharedMemorySize, MMA_SMEM_FUSE);
    cudaFuncSetAttribute(gru_mma<false>,
                         cudaFuncAttributeMaxDynamicSharedMemorySize, MMA_SMEM_PLAIN);
    cudaFuncSetAttribute(gi0_mma,
                         cudaFuncAttributeMaxDynamicSharedMemorySize, GI0_SMEM);
    cudaFuncSetAttribute(gemm_expert<256, true>,
                         cudaFuncAttributeMaxDynamicSharedMemorySize, EXP_SMEM);
    cudaFuncSetAttribute(gemm_expert<512, false>,
                         cudaFuncAttributeMaxDynamicSharedMemorySize, EXP_SMEM);

    const size_t WN  = (size_t)G3 * Hsz;
    const size_t WN0 = (size_t)G3 * Isz;
    const size_t XN  = (size_t)MT * Isz;
    const size_t W1N = (size_t)Ksz * E1sz * Hsz;
    const size_t W2N = (size_t)Ksz * E2sz * E1sz;
    const size_t PHB = (size_t)Bsz * Hsz;

    cvt_split<<<(int)(XN/256), 256>>>(x, xB, xB + XN, (int)XN);
    cvt_split<<<(int)((WN0+255)/256), 256>>>(Wih0, wihB0, wihB0 + WN0, (int)WN0);
    cvt_split<<<(int)(WN/256), 256>>>(Whh0, whhB0, whhB0 + WN, (int)WN);
    cvt_split<<<(int)(WN/256), 256>>>(Wih1, wihB1, wihB1 + WN, (int)WN);
    cvt_split<<<(int)(WN/256), 256>>>(Whh1, whhB1, whhB1 + WN, (int)WN);
    cvt_split<<<(int)(W1N/256), 256>>>(eW1, eW1B, eW1B + W1N, (int)W1N);
    cvt_split<<<(int)(W2N/256), 256>>>(eW2, eW2B, eW2B + W2N, (int)W2N);

    gi0_mma<<<dim3(8, MT/64), 256, GI0_SMEM>>>(xB, xB + XN, wihB0, wihB0 + WN0, gi0);

    gru_mma<true><<<dim3(16, 8), 256, MMA_SMEM_FUSE>>>(
        whhB0, whhB0 + WN, wihB1, wihB1 + WN, gi0, bih0, bhh0,
        hB0, gi1, nullptr, cnt0, gen0);
    gru_mma<false><<<dim3(16, 8), 256, MMA_SMEM_PLAIN>>>(
        whhB1, whhB1 + WN, nullptr, nullptr, gi1, bih1, bhh1,
        hB1, nullptr, z, cnt1, gen1);

    qkernel<<<128, 256>>>(z, cent, qb);
    gemm_expert<256, true><<<dim3(8, 16, 8), 256, EXP_SMEM>>>(
        hB1 + PHB, hB1 + 3*PHB, (size_t)0, eW1B, eW1B + W1N, eb1, E1sz,
        nullptr, e1B, e1B + (size_t)Ksz*Bsz*E1sz);
    gemm_expert<512, false><<<dim3(4, 16, 8), 256, EXP_SMEM>>>(
        e1B, e1B + (size_t)Ksz*Bsz*E1sz, (size_t)Bsz*E1sz, eW2B, eW2B + W2N, eb2, E2sz,
        e2, nullptr, nullptr);
    combine_kernel<<<128, 256>>>(e2, qb, eW3, eb3, out);

    (void)in_sizes; (void)n_in; (void)out_size;
}

// round 15
// speedup vs baseline: 2.9833x; 1.2146x over previous
#include <cuda_runtime.h>
#include <cuda_fp16.h>
#include <cstddef>

#define Bsz  1024
#define Tsz  128
#define Isz  128
#define Hsz  256
#define G3   768
#define Ksz  8
#define E1sz 512
#define E2sz 256
#define MT   (Bsz * Tsz)

typedef unsigned long long u64;
typedef unsigned int u32;

__device__ __forceinline__ float sigmoidf_(float x){ return __fdividef(1.0f, 1.0f + __expf(-x)); }
__device__ __forceinline__ float tanhf_(float x){ return 1.0f - __fdividef(2.0f, __expf(2.0f*x) + 1.0f); }

__device__ __forceinline__ u32 smem_u32(const void* p){
    u32 a; asm("{ .reg .u64 t; cvta.to.shared.u64 t, %1; cvt.u32.u64 %0, t; }" : "=r"(a) : "l"(p)); return a;
}
__device__ __forceinline__ void ldmA(u32 a, u32& r0, u32& r1, u32& r2, u32& r3){
    asm volatile("ldmatrix.sync.aligned.m8n8.x4.shared.b16 {%0,%1,%2,%3},[%4];"
                 : "=r"(r0),"=r"(r1),"=r"(r2),"=r"(r3) : "r"(a));
}
__device__ __forceinline__ void ldmB(u32 a, u32& r0, u32& r1){
    asm volatile("ldmatrix.sync.aligned.m8n8.x2.shared.b16 {%0,%1},[%2];"
                 : "=r"(r0),"=r"(r1) : "r"(a));
}
__device__ __forceinline__ void mma16816(float* d, u32 a0,u32 a1,u32 a2,u32 a3,u32 b0,u32 b1){
    asm volatile("mma.sync.aligned.m16n8k16.row.col.f32.f16.f16.f32 "
                 "{%0,%1,%2,%3},{%4,%5,%6,%7},{%8,%9},{%0,%1,%2,%3};"
                 : "+f"(d[0]),"+f"(d[1]),"+f"(d[2]),"+f"(d[3])
                 : "r"(a0),"r"(a1),"r"(a2),"r"(a3),"r"(b0),"r"(b1));
}
#define SWZ(row, c) ((u32)((((c) ^ ((row) & 7)) << 4)))

// ---------------- scratch ----------------
__device__ float g_gi0[(size_t)Tsz * Bsz * G3];
__device__ float g_gi1[(size_t)Tsz * Bsz * G3];
__device__ __half g_xH[(size_t)MT * Isz];                 // x fp16 (single)
__device__ __half g_WihH0[2][(size_t)G3 * Isz];           // hi, lo
__device__ __half g_WhhH0[2][(size_t)G3 * Hsz];
__device__ __half g_WihH1[2][(size_t)G3 * Hsz];
__device__ __half g_WhhH1[2][(size_t)G3 * Hsz];
__device__ __half g_hH0[2][(size_t)Bsz * Hsz];            // h fp16, ping-pong
__device__ __half g_hH1[2][(size_t)Bsz * Hsz];
__device__ __half g_eW1H[2][(size_t)Ksz * E1sz * Hsz];
__device__ __half g_eW2H[2][(size_t)Ksz * E2sz * E1sz];
__device__ __half g_e1H[(size_t)Ksz * Bsz * E1sz];        // expert hidden fp16
__device__ float g_z[(size_t)Bsz * Hsz];
__device__ float g_q[Bsz * Ksz];
__device__ float g_e2[(size_t)Ksz * Bsz * E2sz];
__device__ unsigned g_cnt0[128], g_gen0[128], g_cnt1[128], g_gen1[128];

__device__ __forceinline__ void grid_bar(unsigned* cnt, volatile unsigned* gen,
                                         unsigned target, unsigned nCTAm1){
    __syncthreads();
    if (threadIdx.x == 0){
        __threadfence();
        if (atomicAdd(cnt, 1u) == nCTAm1){
            atomicExch(cnt, 0u); __threadfence(); *gen = target;
        } else { while (*gen < target) { } }
        __threadfence();
    }
    __syncthreads();
}

// fp32 -> fp16 hi/lo split (weights)
__global__ void __launch_bounds__(256) cvt_split(
    const float* __restrict__ in, __half* __restrict__ hi,
    __half* __restrict__ lo, int n)
{
    int i = blockIdx.x * 256 + threadIdx.x;
    if (i < n){
        float v = in[i];
        __half h = __float2half_rn(v);
        hi[i] = h;
        lo[i] = __float2half_rn(v - __half2float(h));
    }
}
// fp32 -> fp16 single (x)
__global__ void __launch_bounds__(256) cvt_h(
    const float* __restrict__ in, __half* __restrict__ out, int n)
{
    int i = blockIdx.x * 256 + threadIdx.x;
    if (i < n) out[i] = __float2half_rn(in[i]);
}

// ---------------------------------------------------------------------------
// mma_multi: load A frags once per k-chunk, feed up to 4 B operands.
// ---------------------------------------------------------------------------
template<int NOPS, int KK, int RS, int F>
__device__ __forceinline__ void mma_multi(
    char* Asm,
    char* B0, float (&o0)[2][F][4], char* B1, float (&o1)[2][F][4],
    char* B2, float (&o2)[2][F][4], char* B3, float (&o3)[2][F][4],
    int lane, int wM, int wN)
{
    u32 aB = smem_u32(Asm);
    u32 bA0 = smem_u32(B0);
    u32 bA1 = (NOPS > 1) ? smem_u32(B1) : 0;
    u32 bA2 = (NOPS > 2) ? smem_u32(B2) : 0;
    u32 bA3 = (NOPS > 3) ? smem_u32(B3) : 0;
    const int ar0 = wM*32 + (lane & 15), ar1 = ar0 + 16;
    const int ah = lane >> 4;
    const int br = wN*(8*F) + (lane & 7);
    const int bh = (lane >> 3) & 1;
    #pragma unroll
    for (int kk = 0; kk < KK; kk++){
        int ac = kk*2 + ah, bc = kk*2 + bh;
        u32 x0,x1,x2,x3, y0,y1,y2,y3;
        ldmA(aB + (u32)(ar0*RS) + SWZ(ar0, ac), x0,x1,x2,x3);
        ldmA(aB + (u32)(ar1*RS) + SWZ(ar1, ac), y0,y1,y2,y3);
        #pragma unroll
        for (int f = 0; f < F; f++){
            int brr = br + f*8;
            u32 b0,b1;
            ldmB(bA0 + (u32)(brr*RS) + SWZ(brr, bc), b0,b1);
            mma16816(o0[0][f], x0,x1,x2,x3, b0,b1);
            mma16816(o0[1][f], y0,y1,y2,y3, b0,b1);
            if (NOPS > 1){
                ldmB(bA1 + (u32)(brr*RS) + SWZ(brr, bc), b0,b1);
                mma16816(o1[0][f], x0,x1,x2,x3, b0,b1);
                mma16816(o1[1][f], y0,y1,y2,y3, b0,b1);
            }
            if (NOPS > 2){
                ldmB(bA2 + (u32)(brr*RS) + SWZ(brr, bc), b0,b1);
                mma16816(o2[0][f], x0,x1,x2,x3, b0,b1);
                mma16816(o2[1][f], y0,y1,y2,y3, b0,b1);
            }
            if (NOPS > 3){
                ldmB(bA3 + (u32)(brr*RS) + SWZ(brr, bc), b0,b1);
                mma16816(o3[0][f], x0,x1,x2,x3, b0,b1);
                mma16816(o3[1][f], y0,y1,y2,y3, b0,b1);
            }
        }
    }
}

// A fill: 64 rows x 256 fp16 (32KB), swizzled, RS=512
__device__ __forceinline__ void fill_A(char* Asm, const __half* src, int m0, int tid){
    #pragma unroll
    for (int i = 0; i < 8; i++){
        int id = tid + i*256, row = id >> 5, c = id & 31;
        uint4 v = __ldcg(reinterpret_cast<const uint4*>(src + (size_t)(m0+row)*Hsz) + c);
        *reinterpret_cast<uint4*>(Asm + (size_t)row*512 + SWZ(row, c)) = v;
    }
}
// chain B fill, gate-major within each warp's 24-col span
__device__ __forceinline__ void fill_Bg(char* dst, const __half* W, int n0, int tid){
    for (int i = tid; i < 96*32; i += 256){
        int j = i >> 5, c = i & 31;
        int wrow = ((j >> 3) % 3)*Hsz + n0 + (j/24)*8 + (j & 7);
        uint4 v = *(reinterpret_cast<const uint4*>(W + (size_t)wrow*Hsz) + c);
        *reinterpret_cast<uint4*>(dst + (size_t)j*512 + SWZ(j, c)) = v;
    }
}
template<int F>
__device__ __forceinline__ void zero_acc(float (&a)[2][F][4]){
    #pragma unroll
    for (int m = 0; m < 2; m++)
        #pragma unroll
        for (int f = 0; f < F; f++)
            #pragma unroll
            for (int q = 0; q < 4; q++) a[m][f][q] = 0.0f;
}
__device__ __forceinline__ void store_nat(float* ghsm, float acc[2][3][4], int lane, int wM, int wN){
    #pragma unroll
    for (int m = 0; m < 2; m++)
        #pragma unroll
        for (int f = 0; f < 3; f++){
            int r0 = wM*32 + m*16 + (lane >> 2);
            int j0 = wN*24 + f*8 + 2*(lane & 3);
            int n0c = (j0 % 3)*32 + j0/3;
            int n1c = ((j0+1) % 3)*32 + (j0+1)/3;
            ghsm[r0*96 + n0c]     = acc[m][f][0];
            ghsm[r0*96 + n1c]     = acc[m][f][1];
            ghsm[(r0+8)*96 + n0c] = acc[m][f][2];
            ghsm[(r0+8)*96 + n1c] = acc[m][f][3];
        }
}

// ---------------------------------------------------------------------------
// gi0 = x @ Wih0^T : fp16 2-pass. Grid (8, 2048). smem 64KB.
// ---------------------------------------------------------------------------
__global__ void __launch_bounds__(256) gi0_mma(
    const __half* __restrict__ xH,
    const __half* __restrict__ wHi, const __half* __restrict__ wLo,
    float* __restrict__ gi0)
{
    extern __shared__ char smc[];
    char* Bhi = smc;                 // 24KB
    char* Blo = smc + 24*1024;       // 24KB
    char* Asm = smc + 48*1024;       // 16KB
    float* ghsm = reinterpret_cast<float*>(smc);   // reuse Bhi region post-MMA (24KB)

    const int tid = threadIdx.x, lane = tid & 31, w = tid >> 5;
    const int wM = w >> 2, wN = w & 3;
    const int n0 = blockIdx.x * 32, m0 = blockIdx.y * 64;
    const size_t PG = (size_t)Bsz * G3;

    for (int i = tid; i < 96*16; i += 256){
        int j = i >> 4, c = i & 15;
        int wrow = (j % 3)*Hsz + n0 + (j/3);
        *reinterpret_cast<uint4*>(Bhi + (size_t)j*256 + SWZ(j, c)) =
            *(reinterpret_cast<const uint4*>(wHi + (size_t)wrow*Isz) + c);
        *reinterpret_cast<uint4*>(Blo + (size_t)j*256 + SWZ(j, c)) =
            *(reinterpret_cast<const uint4*>(wLo + (size_t)wrow*Isz) + c);
    }
    #pragma unroll
    for (int i = 0; i < 4; i++){
        int id = tid + i*256, row = id >> 4, c = id & 15;
        *reinterpret_cast<uint4*>(Asm + (size_t)row*256 + SWZ(row, c)) =
            *(reinterpret_cast<const uint4*>(xH + (size_t)(m0+row)*Isz) + c);
    }
    __syncthreads();

    float acc[2][3][4];
    zero_acc(acc);
    mma_multi<2, 8, 256, 3>(Asm, Bhi, acc, Blo, acc, Bhi, acc, Bhi, acc, lane, wM, wN);
    __syncthreads();
    store_nat(ghsm, acc, lane, wM, wN);
    __syncthreads();

    const int b = m0 >> 7, t0 = m0 & 127;
    #pragma unroll
    for (int i = 0; i < 6; i++){
        int fid = tid + i*256;
        int row = fid / 24, cq = fid % 24;
        int g = cq >> 3, hc4 = (cq & 7)*4;
        float4 v = *reinterpret_cast<const float4*>(ghsm + row*96 + g*32 + hc4);
        *reinterpret_cast<float4*>(gi0 + (size_t)(t0+row)*PG + (size_t)b*G3 + g*256 + n0 + hc4) = v;
    }
}

// ---------------------------------------------------------------------------
// Persistent HMMA GRU chain, fp16 2-pass: single-plane A, one mma_multi call,
// gate-major B, register-local epilogue, gi prefetch.
// ---------------------------------------------------------------------------
template<bool FUSE>
__global__ void __launch_bounds__(256) gru_mma(
    const __half* __restrict__ WhhHi, const __half* __restrict__ WhhLo,
    const __half* __restrict__ WihHi, const __half* __restrict__ WihLo,
    const float* __restrict__ giAll, const float* __restrict__ bih,
    const float* __restrict__ bhh, __half* __restrict__ hB,
    float* __restrict__ gi1out, float* __restrict__ zout,
    unsigned* cntArr, unsigned* genArr)
{
    extern __shared__ char smc[];
    __shared__ float sB[192];
    char* B_hh_hi = smc;
    char* B_hh_lo = smc + 48*1024;
    char* B_ih_hi = smc + 96*1024;     // FUSE only
    char* B_ih_lo = smc + 144*1024;    // FUSE only
    char* A1 = smc + (FUSE ? 192 : 96)*1024;

    const int tid = threadIdx.x, lane = tid & 31, w = tid >> 5;
    const int wM = w >> 2, wN = w & 3;
    const int m0 = blockIdx.x * 64, n0 = blockIdx.y * 32;
    const size_t PG = (size_t)Bsz * G3, PHB = (size_t)Bsz * Hsz;
    unsigned* cnt = cntArr + blockIdx.x * 8;
    volatile unsigned* gen = genArr + blockIdx.x * 8;

    fill_Bg(B_hh_hi, WhhHi, n0, tid);
    fill_Bg(B_hh_lo, WhhLo, n0, tid);
    if constexpr (FUSE){
        fill_Bg(B_ih_hi, WihHi, n0, tid);
        fill_Bg(B_ih_lo, WihLo, n0, tid);
    }
    if (tid < 192){
        int g = tid >> 5, c = tid & 31;
        sB[tid] = (g < 3) ? bih[g*Hsz + n0 + c] : bhh[(g-3)*Hsz + n0 + c];
    }

    const int cl = wN*8 + 2*(lane & 3);       // local col base (even)
    const int colb = n0 + cl;
    const int rloc = wM*32 + (lane >> 2);
    float h_own[2][2][2];
    #pragma unroll
    for (int m = 0; m < 2; m++)
        #pragma unroll
        for (int hr = 0; hr < 2; hr++){ h_own[m][hr][0] = 0.0f; h_own[m][hr][1] = 0.0f; }

    const unsigned gbase = *gen;
    __syncthreads();

    for (int t = 0; t < Tsz; t++){
        float accG[2][3][4], accI[2][3][4];
        zero_acc(accG);
        if constexpr (FUSE) zero_acc(accI);
        float2 giv[2][2][3];

        if (t > 0){
            int pp = (t - 1) & 1;
            fill_A(A1, hB + (size_t)pp * PHB, m0, tid);
            __syncthreads();
            // gi prefetch in flight during MMA
            #pragma unroll
            for (int m = 0; m < 2; m++)
                #pragma unroll
                for (int hr = 0; hr < 2; hr++){
                    const float* gp = giAll + (size_t)t*PG
                        + (size_t)(m0 + rloc + m*16 + hr*8)*G3 + colb;
                    #pragma unroll
                    for (int g = 0; g < 3; g++)
                        giv[m][hr][g] = *reinterpret_cast<const float2*>(gp + g*256);
                }
            if constexpr (FUSE)
                mma_multi<4,16,512,3>(A1, B_hh_hi, accG, B_hh_lo, accG,
                                      B_ih_hi, accI, B_ih_lo, accI, lane, wM, wN);
            else
                mma_multi<2,16,512,3>(A1, B_hh_hi, accG, B_hh_lo, accG,
                                      B_hh_hi, accG, B_hh_hi, accG, lane, wM, wN);
        } else {
            #pragma unroll
            for (int m = 0; m < 2; m++)
                #pragma unroll
                for (int hr = 0; hr < 2; hr++){
                    const float* gp = giAll + (size_t)(m0 + rloc + m*16 + hr*8)*G3 + colb;
                    #pragma unroll
                    for (int g = 0; g < 3; g++)
                        giv[m][hr][g] = *reinterpret_cast<const float2*>(gp + g*256);
                }
        }

        // ---- register-local epilogue ----
        {
            int pp2 = t & 1;
            __half* hW = hB + (size_t)pp2 * PHB;
            #pragma unroll
            for (int m = 0; m < 2; m++)
                #pragma unroll
                for (int hr = 0; hr < 2; hr++){
                    int row = m0 + rloc + m*16 + hr*8;
                    float hv2[2];
                    #pragma unroll
                    for (int cc = 0; cc < 2; cc++){
                        int q = hr*2 + cc;
                        float gr = (t > 0) ? accG[m][0][q] : 0.0f;
                        float gz = (t > 0) ? accG[m][1][q] : 0.0f;
                        float gn = (t > 0) ? accG[m][2][q] : 0.0f;
                        float gir = cc ? giv[m][hr][0].y : giv[m][hr][0].x;
                        float giz = cc ? giv[m][hr][1].y : giv[m][hr][1].x;
                        float gin = cc ? giv[m][hr][2].y : giv[m][hr][2].x;
                        float rg = sigmoidf_(gir + sB[cl+cc]      + gr + sB[96+cl+cc]);
                        float zg = sigmoidf_(giz + sB[32+cl+cc]   + gz + sB[128+cl+cc]);
                        float ng = tanhf_(gin + sB[64+cl+cc]      + rg*(gn + sB[160+cl+cc]));
                        float hv = (1.0f - zg)*ng + zg*h_own[m][hr][cc];
                        h_own[m][hr][cc] = hv;
                        hv2[cc] = hv;
                    }
                    __half2 hp;
                    hp.x = __float2half_rn(hv2[0]);
                    hp.y = __float2half_rn(hv2[1]);
                    *reinterpret_cast<u32*>(hW + (size_t)row*Hsz + colb) =
                        *reinterpret_cast<u32*>(&hp);
                    if (!FUSE && t == Tsz-1)
                        *reinterpret_cast<float2*>(zout + (size_t)row*Hsz + colb) =
                            make_float2(hv2[0], hv2[1]);
                    if (FUSE && t > 0){
                        float* go = gi1out + (size_t)(t-1)*PG + (size_t)row*G3;
                        #pragma unroll
                        for (int g = 0; g < 3; g++)
                            *reinterpret_cast<float2*>(go + g*256 + colb) =
                                make_float2(accI[m][g][hr*2], accI[m][g][hr*2+1]);
                    }
                }
        }

        grid_bar(cnt, gen, gbase + (unsigned)t + 1u, 7u);
    }

    // ---- FUSE tail: gi1[127] = h[127] @ Wih1^T ----
    if constexpr (FUSE){
        float accI[2][3][4];
        zero_acc(accI);
        fill_A(A1, hB + (size_t)((Tsz - 1) & 1) * PHB, m0, tid);
        __syncthreads();
        mma_multi<2,16,512,3>(A1, B_ih_hi, accI, B_ih_lo, accI,
                              B_ih_hi, accI, B_ih_hi, accI, lane, wM, wN);
        #pragma unroll
        for (int m = 0; m < 2; m++)
            #pragma unroll
            for (int hr = 0; hr < 2; hr++){
                int row = m0 + rloc + m*16 + hr*8;
                float* go = gi1out + (size_t)(Tsz-1)*PG + (size_t)row*G3;
                #pragma unroll
                for (int g = 0; g < 3; g++)
                    *reinterpret_cast<float2*>(go + g*256 + colb) =
                        make_float2(accI[m][g][hr*2], accI[m][g][hr*2+1]);
            }
    }
}

// ---------------------------------------------------------------------------
// Expert GEMM fp16 2-pass: C[e] = relu(A[e] @ W[e]^T + bias[e])
// ---------------------------------------------------------------------------
template<int KDIM, bool EMIT_HALF>
__global__ void __launch_bounds__(256) gemm_expert(
    const __half* __restrict__ aH, size_t aExpStride,
    const __half* __restrict__ wHi, const __half* __restrict__ wLo,
    const float* __restrict__ bias, int N,
    float* __restrict__ outF, __half* __restrict__ outH)
{
    extern __shared__ char smc[];
    char* Asm = smc;                 // 16KB
    char* Bh  = smc + 16*1024;       // 16KB
    char* Bl  = smc + 32*1024;       // 16KB

    const int tid = threadIdx.x, lane = tid & 31, w = tid >> 5;
    const int wM = w >> 2, wN = w & 3;
    const int e = blockIdx.z;
    const int n0 = blockIdx.x * 64, m0 = blockIdx.y * 64;
    const __half* Ap  = aH  + (size_t)e * aExpStride;
    const __half* Whp = wHi + (size_t)e * N * KDIM;
    const __half* Wlp = wLo + (size_t)e * N * KDIM;

    float acc[2][2][4];
    zero_acc(acc);

    for (int kc = 0; kc < KDIM; kc += 128){
        if (kc) __syncthreads();
        #pragma unroll
        for (int i = 0; i < 4; i++){
            int id = tid + i*256, r = id >> 4, c = id & 15;
            *reinterpret_cast<uint4*>(Asm + (size_t)r*256 + SWZ(r, c)) =
                *(reinterpret_cast<const uint4*>(Ap + (size_t)(m0+r)*KDIM + kc) + c);
            *reinterpret_cast<uint4*>(Bh + (size_t)r*256 + SWZ(r, c)) =
                *(reinterpret_cast<const uint4*>(Whp + (size_t)(n0+r)*KDIM + kc) + c);
            *reinterpret_cast<uint4*>(Bl + (size_t)r*256 + SWZ(r, c)) =
                *(reinterpret_cast<const uint4*>(Wlp + (size_t)(n0+r)*KDIM + kc) + c);
        }
        __syncthreads();
        mma_multi<2, 8, 256, 2>(Asm, Bh, acc, Bl, acc, Bh, acc, Bh, acc, lane, wM, wN);
    }

    const size_t ob = (size_t)e * Bsz * N;
    #pragma unroll
    for (int m = 0; m < 2; m++)
        #pragma unroll
        for (int f = 0; f < 2; f++){
            int r0 = m0 + wM*32 + m*16 + (lane >> 2);
            int c0 = n0 + wN*16 + f*8 + 2*(lane & 3);
            float b0v = bias[e*N + c0], b1v = bias[e*N + c0 + 1];
            #pragma unroll
            for (int hrow = 0; hrow < 2; hrow++){
                int r = r0 + hrow*8;
                float v0 = fmaxf(acc[m][f][hrow*2+0] + b0v, 0.0f);
                float v1 = fmaxf(acc[m][f][hrow*2+1] + b1v, 0.0f);
                if constexpr (EMIT_HALF){
                    __half2 hp;
                    hp.x = __float2half_rn(v0);
                    hp.y = __float2half_rn(v1);
                    *reinterpret_cast<u32*>(outH + ob + (size_t)r*N + c0) =
                        *reinterpret_cast<u32*>(&hp);
                } else {
                    *reinterpret_cast<float2*>(outF + ob + (size_t)r*N + c0) = make_float2(v0, v1);
                }
            }
        }
}

// ---------------- q / combine (proven) ----------------
__global__ void __launch_bounds__(256) qkernel(
    const float* __restrict__ z, const float* __restrict__ cent, float* __restrict__ q)
{
    int warp = threadIdx.x >> 5, lane = threadIdx.x & 31;
    int b = blockIdx.x*8 + warp;
    float zr[8];
    #pragma unroll
    for (int i = 0; i < 8; i++) zr[i] = z[(size_t)b*Hsz + lane + 32*i];
    float s = 0.0f;
    for (int k = 0; k < Ksz; k++){
        float d = 0.0f;
        #pragma unroll
        for (int i = 0; i < 8; i++){
            float t = zr[i] - cent[k*Hsz + lane + 32*i];
            d = fmaf(t, t, d);
        }
        #pragma unroll
        for (int off = 16; off; off >>= 1) d += __shfl_xor_sync(0xffffffffu, d, off);
        if (lane == k) s = 1.0f / (1.0f + d);
    }
    float tot = s;
    #pragma unroll
    for (int off = 16; off; off >>= 1) tot += __shfl_xor_sync(0xffffffffu, tot, off);
    if (lane < Ksz) q[(size_t)b*Ksz + lane] = s / tot;
}

__global__ void __launch_bounds__(256) combine_kernel(
    const float* __restrict__ h2, const float* __restrict__ q,
    const float* __restrict__ eW3, const float* __restrict__ eb3, float* __restrict__ out)
{
    int warp = threadIdx.x >> 5, lane = threadIdx.x & 31;
    int b = blockIdx.x*8 + warp;
    float acc[Ksz][2];
    #pragma unroll
    for (int k = 0; k < Ksz; k++){ acc[k][0] = 0.0f; acc[k][1] = 0.0f; }
    for (int f = lane; f < E2sz; f += 32){
        #pragma unroll
        for (int k = 0; k < Ksz; k++){
            float hv = h2[((size_t)k*Bsz + b)*E2sz + f];
            acc[k][0] = fmaf(hv, eW3[(size_t)(k*2+0)*E2sz + f], acc[k][0]);
            acc[k][1] = fmaf(hv, eW3[(size_t)(k*2+1)*E2sz + f], acc[k][1]);
        }
    }
    #pragma unroll
    for (int k = 0; k < Ksz; k++)
        #pragma unroll
        for (int c = 0; c < 2; c++)
            #pragma unroll
            for (int off = 16; off; off >>= 1)
                acc[k][c] += __shfl_xor_sync(0xffffffffu, acc[k][c], off);
    if (lane == 0){
        float p0 = 0.0f, p1 = 0.0f;
        #pragma unroll
        for (int k = 0; k < Ksz; k++){
            float qq = q[(size_t)b*Ksz + k];
            p0 = fmaf(qq, acc[k][0] + eb3[k*2+0], p0);
            p1 = fmaf(qq, acc[k][1] + eb3[k*2+1], p1);
        }
        out[b*2+0] = p0; out[b*2+1] = p1;
    }
}

// ---------------------------------------------------------------------------
#define MMA_SMEM_FUSE  ((192 + 32) * 1024)
#define MMA_SMEM_PLAIN ((96 + 32) * 1024)
#define GI0_SMEM       (64 * 1024)
#define EXP_SMEM       (48 * 1024)

extern "C" void kernel_launch(void* const* d_in, const int* in_sizes, int n_in,
                              void* d_out, int out_size)
{
    const float* x    = (const float*)d_in[0];
    const float* Wih0 = (const float*)d_in[1];
    const float* Whh0 = (const float*)d_in[2];
    const float* bih0 = (const float*)d_in[3];
    const float* bhh0 = (const float*)d_in[4];
    const float* Wih1 = (const float*)d_in[5];
    const float* Whh1 = (const float*)d_in[6];
    const float* bih1 = (const float*)d_in[7];
    const float* bhh1 = (const float*)d_in[8];
    const float* cent = (const float*)d_in[9];
    const float* eW1  = (const float*)d_in[10];
    const float* eb1  = (const float*)d_in[11];
    const float* eW2  = (const float*)d_in[12];
    const float* eb2  = (const float*)d_in[13];
    const float* eW3  = (const float*)d_in[14];
    const float* eb3  = (const float*)d_in[15];
    float* out = (float*)d_out;

    float *gi0, *gi1, *z, *qb, *e2;
    __half *xH, *wihH0, *whhH0, *wihH1, *whhH1, *hH0, *hH1, *eW1H, *eW2H, *e1H;
    unsigned *cnt0, *gen0, *cnt1, *gen1;
    cudaGetSymbolAddress((void**)&gi0,   g_gi0);
    cudaGetSymbolAddress((void**)&gi1,   g_gi1);
    cudaGetSymbolAddress((void**)&xH,    g_xH);
    cudaGetSymbolAddress((void**)&wihH0, g_WihH0);
    cudaGetSymbolAddress((void**)&whhH0, g_WhhH0);
    cudaGetSymbolAddress((void**)&wihH1, g_WihH1);
    cudaGetSymbolAddress((void**)&whhH1, g_WhhH1);
    cudaGetSymbolAddress((void**)&hH0,   g_hH0);
    cudaGetSymbolAddress((void**)&hH1,   g_hH1);
    cudaGetSymbolAddress((void**)&eW1H,  g_eW1H);
    cudaGetSymbolAddress((void**)&eW2H,  g_eW2H);
    cudaGetSymbolAddress((void**)&e1H,   g_e1H);
    cudaGetSymbolAddress((void**)&z,     g_z);
    cudaGetSymbolAddress((void**)&qb,    g_q);
    cudaGetSymbolAddress((void**)&e2,    g_e2);
    cudaGetSymbolAddress((void**)&cnt0,  g_cnt0);
    cudaGetSymbolAddress((void**)&gen0,  g_gen0);
    cudaGetSymbolAddress((void**)&cnt1,  g_cnt1);
    cudaGetSymbolAddress((void**)&gen1,  g_gen1);

    cudaFuncSetAttribute(gru_mma<true>,
                         cudaFuncAttributeMaxDynamicSharedMemorySize, MMA_SMEM_FUSE);
    cudaFuncSetAttribute(gru_mma<false>,
                         cudaFuncAttributeMaxDynamicSharedMemorySize, MMA_SMEM_PLAIN);
    cudaFuncSetAttribute(gi0_mma,
                         cudaFuncAttributeMaxDynamicSharedMemorySize, GI0_SMEM);
    cudaFuncSetAttribute(gemm_expert<256, true>,
                         cudaFuncAttributeMaxDynamicSharedMemorySize, EXP_SMEM);
    cudaFuncSetAttribute(gemm_expert<512, false>,
                         cudaFuncAttributeMaxDynamicSharedMemorySize, EXP_SMEM);

    const size_t WN  = (size_t)G3 * Hsz;
    const size_t WN0 = (size_t)G3 * Isz;
    const size_t XN  = (size_t)MT * Isz;
    const size_t W1N = (size_t)Ksz * E1sz * Hsz;
    const size_t W2N = (size_t)Ksz * E2sz * E1sz;
    const size_t PHB = (size_t)Bsz * Hsz;

    cvt_h<<<(int)(XN/256), 256>>>(x, xH, (int)XN);
    cvt_split<<<(int)((WN0+255)/256), 256>>>(Wih0, wihH0, wihH0 + WN0, (int)WN0);
    cvt_split<<<(int)(WN/256), 256>>>(Whh0, whhH0, whhH0 + WN, (int)WN);
    cvt_split<<<(int)(WN/256), 256>>>(Wih1, wihH1, wihH1 + WN, (int)WN);
    cvt_split<<<(int)(WN/256), 256>>>(Whh1, whhH1, whhH1 + WN, (int)WN);
    cvt_split<<<(int)(W1N/256), 256>>>(eW1, eW1H, eW1H + W1N, (int)W1N);
    cvt_split<<<(int)(W2N/256), 256>>>(eW2, eW2H, eW2H + W2N, (int)W2N);

    gi0_mma<<<dim3(8, MT/64), 256, GI0_SMEM>>>(xH, wihH0, wihH0 + WN0, gi0);

    gru_mma<true><<<dim3(16, 8), 256, MMA_SMEM_FUSE>>>(
        whhH0, whhH0 + WN, wihH1, wihH1 + WN, gi0, bih0, bhh0,
        hH0, gi1, nullptr, cnt0, gen0);
    gru_mma<false><<<dim3(16, 8), 256, MMA_SMEM_PLAIN>>>(
        whhH1, whhH1 + WN, nullptr, nullptr, gi1, bih1, bhh1,
        hH1, nullptr, z, cnt1, gen1);

    qkernel<<<128, 256>>>(z, cent, qb);
    // z fp16 = hH1 plane (127 & 1) = 1 after 128 steps
    gemm_expert<256, true><<<dim3(8, 16, 8), 256, EXP_SMEM>>>(
        hH1 + PHB, (size_t)0, eW1H, eW1H + W1N, eb1, E1sz,
        nullptr, e1H);
    gemm_expert<512, false><<<dim3(4, 16, 8), 256, EXP_SMEM>>>(
        e1H, (size_t)Bsz*E1sz, eW2H, eW2H + W2N, eb2, E2sz,
        e2, nullptr);
    combine_kernel<<<128, 256>>>(e2, qb, eW3, eb3, out);

    (void)in_sizes; (void)n_in; (void)out_size;
}